// round 5
// baseline (speedup 1.0000x reference)
#include <cuda_runtime.h>
#include <cuda_fp16.h>
#include <cstdint>
#include <cstddef>

#define DI __device__ __forceinline__

// ---------------- problem constants ----------------
constexpr int BB = 8, CI = 512, CO = 512, KW = 5, LL = 4096;

// ---------------- GEMM tiling ----------------
constexpr int NIT = 40;                      // ic(8) x kw(5)
constexpr int TILE_B = 16384;                // A tile: 128 rows x 128B
constexpr int BROWSBUF = 264;                // B slab rows per ic
constexpr int BBUF = BROWSBUF * 128;         // 33792 B
constexpr int ASTAGE = 3;
constexpr int GEMM_SMEM = ASTAGE * TILE_B + 2 * BBUF;   // 116736

constexpr int BROWS = 4224;                  // g_Bx rows (33*128)

// ---------------- device scratch ----------------
// x rows: [b][ic(8)][gl(4224)] x 64 halfs (128B rows), swizzle phase = gl&7; l = gl-2
__device__ __half g_Bx[(size_t)BB * 8 * BROWS * 64];
// weight tiles (batch-independent): [k][oT(4)][ic(8)], 128x128B swizzled tiles
__device__ __half g_W[(size_t)KW * 4 * 8 * 8192];
__device__ float  g_avg[BB * CI];
__device__ float  g_ka[BB * KW];
__device__ float  g_scale[BB * CO];

// ---------------- helpers ----------------
DI uint32_t smem_u32(const void* p) {
    uint32_t a;
    asm("{ .reg .u64 t; cvta.to.shared.u64 t, %1; cvt.u32.u64 %0, t; }" : "=r"(a) : "l"(p));
    return a;
}
DI uint32_t swz(uint32_t off) { return off ^ ((off >> 3) & 0x70); }
DI void cp16(uint32_t dst, const void* src) {
    asm volatile("cp.async.cg.shared.global [%0], [%1], 16;" :: "r"(dst), "l"(src) : "memory");
}
DI void cp_commit() { asm volatile("cp.async.commit_group;" ::: "memory"); }
template <int N> DI void cp_wait() { asm volatile("cp.async.wait_group %0;" :: "n"(N) : "memory"); }

DI void ldmx4(uint32_t& r0, uint32_t& r1, uint32_t& r2, uint32_t& r3, uint32_t a) {
    asm volatile("ldmatrix.sync.aligned.m8n8.x4.shared.b16 {%0,%1,%2,%3}, [%4];"
                 : "=r"(r0), "=r"(r1), "=r"(r2), "=r"(r3) : "r"(a));
}
DI void mma16816(float* c, const uint32_t* a, const uint32_t* b) {
    asm volatile(
        "mma.sync.aligned.m16n8k16.row.col.f32.f16.f16.f32 "
        "{%0,%1,%2,%3}, {%4,%5,%6,%7}, {%8,%9}, {%0,%1,%2,%3};"
        : "+f"(c[0]), "+f"(c[1]), "+f"(c[2]), "+f"(c[3])
        : "r"(a[0]), "r"(a[1]), "r"(a[2]), "r"(a[3]), "r"(b[0]), "r"(b[1]));
}

// ---------------- kernel 1: per-(b,c) mean over L ----------------
__global__ void k_avg(const float* __restrict__ x) {
    int row = blockIdx.x;
    const float4* p = (const float4*)(x + (size_t)row * LL);
    float s = 0.f;
#pragma unroll
    for (int q = 0; q < 4; ++q) {
        float4 v = p[threadIdx.x + q * 256];
        s += (v.x + v.y) + (v.z + v.w);
    }
#pragma unroll
    for (int o = 16; o; o >>= 1) s += __shfl_xor_sync(0xFFFFFFFFu, s, o);
    __shared__ float ws[8];
    if ((threadIdx.x & 31) == 0) ws[threadIdx.x >> 5] = s;
    __syncthreads();
    if (threadIdx.x == 0) {
        float t = 0.f;
#pragma unroll
        for (int w = 0; w < 8; ++w) t += ws[w];
        g_avg[row] = t * (1.f / (float)LL);
    }
}

// ---------------- kernel 2: attention branches ----------------
__global__ void k_att(
    const float* ka_w1, const float* ka_b1, const float* ka_w2, const float* ka_b2,
    const float* sa_w1, const float* sa_b1, const float* sa_w2, const float* sa_b2,
    const float* ia_w1, const float* ia_b1, const float* ia_w2, const float* ia_b2,
    const float* oa_w1, const float* oa_b1, const float* oa_w2, const float* oa_b2) {
    __shared__ float avgs[CI];
    __shared__ float h[4][128];
    __shared__ float sav;
    int b = blockIdx.x, t = threadIdx.x;   // 512 threads
    avgs[t] = g_avg[b * CI + t];
    __syncthreads();

    int br = t >> 7, row = t & 127;
    const float* w1 = br == 0 ? ka_w1 : br == 1 ? sa_w1 : br == 2 ? ia_w1 : oa_w1;
    const float* b1 = br == 0 ? ka_b1 : br == 1 ? sa_b1 : br == 2 ? ia_b1 : oa_b1;
    float s = b1[row];
    const float* wr = w1 + (size_t)row * CI;
#pragma unroll 8
    for (int u = 0; u < CI; ++u) s += avgs[u] * wr[u];
    h[br][row] = fmaxf(s, 0.f);
    __syncthreads();

    float s2 = oa_b2[t];
    const float* w2r = oa_w2 + (size_t)t * 128;
#pragma unroll 8
    for (int r = 0; r < 128; ++r) s2 += h[3][r] * w2r[r];
    float oav = 1.f / (1.f + expf(-s2));

    float s3 = ia_b2[t];
    const float* w3r = ia_w2 + (size_t)t * 128;
#pragma unroll 8
    for (int r = 0; r < 128; ++r) s3 += h[2][r] * w3r[r];
    float iav = 1.f / (1.f + expf(-s3));

    if (t < KW) {
        float s4 = ka_b2[t];
        const float* w4r = ka_w2 + (size_t)t * 128;
#pragma unroll 8
        for (int r = 0; r < 128; ++r) s4 += h[0][r] * w4r[r];
        g_ka[b * KW + t] = 1.f / (1.f + expf(-s4));
    }
    if (t == 256) {
        float s5 = sa_b2[0];
#pragma unroll 8
        for (int r = 0; r < 128; ++r) s5 += h[1][r] * sa_w2[r];
        sav = 1.f / (1.f + expf(-s5));
    }
    __syncthreads();
    g_scale[b * CO + t] = sav * iav * oav;
}

// ---------------- kernel 3: weight -> fp16 swizzled tiles (no ka) ----------------
__global__ void k_prepW(const float* __restrict__ w) {
    int bx = blockIdx.x;                 // k*32 + oT*8 + ic, 160 blocks
    int k = bx >> 5, oT = (bx >> 3) & 3, ic = bx & 7;
    int o = oT * 128 + threadIdx.x;      // 128 threads = rows
    char* tile = (char*)g_W + (size_t)bx * TILE_B;
    const float* wr = w + ((size_t)o * CI + ic * 64) * KW + k;
#pragma unroll 8
    for (int j = 0; j < 32; ++j) {
        float v0 = wr[(size_t)(2 * j) * KW];
        float v1 = wr[(size_t)(2 * j + 1) * KW];
        __half2 hv = __floats2half2_rn(v0, v1);
        *(uint32_t*)(tile + swz((uint32_t)threadIdx.x * 128 + j * 4)) = *(uint32_t*)&hv;
    }
}

// ---------------- kernel 4: x rows -> fp16, transposed, global-phase swizzled ----
__global__ void k_prepB(const float* __restrict__ x) {
    __shared__ float xs[128][65];        // [row offset][channel]
    int bx = blockIdx.x;                 // b*(8*33) + ic*33 + g
    int g = bx % 33;
    int ic = (bx / 33) & 7;
    int b = bx / (33 * 8);
    int tid = threadIdx.x;               // 256 threads
    for (int e = tid; e < 64 * 128; e += 256) {
        int c = e >> 7, off = e & 127;
        int l = g * 128 - 2 + off;
        float v = 0.f;
        if (l >= 0 && l < LL)
            v = x[((size_t)(b * CI + ic * 64 + c)) * LL + l];
        xs[off][c] = v;
    }
    __syncthreads();
    char* base = (char*)g_Bx + ((size_t)(b * 8 + ic) * BROWS + (size_t)g * 128) * 128;
#pragma unroll
    for (int q = 0; q < 4; ++q) {
        int idx = tid + q * 256;         // 1024: 128 rows x 8 chunks
        int r = idx >> 3, j = idx & 7;
        uint32_t u[4];
#pragma unroll
        for (int p = 0; p < 4; ++p) {
            __half2 hv = __floats2half2_rn(xs[r][j * 8 + 2 * p], xs[r][j * 8 + 2 * p + 1]);
            u[p] = *(uint32_t*)&hv;
        }
        uint32_t off = (uint32_t)(j * 16) ^ (uint32_t)((r & 7) * 16);
        *(uint4*)(base + (size_t)r * 128 + off) = make_uint4(u[0], u[1], u[2], u[3]);
    }
}

// ---------------- kernel 5: HMMA GEMM (BM128 x BN256), B slab reuse ----------------
__global__ void __launch_bounds__(512, 1)
k_gemm(const float* __restrict__ bias, float* __restrict__ out) {
    extern __shared__ char sm[];
    uint32_t sbase = smem_u32(sm);
    uint32_t bbase = sbase + ASTAGE * TILE_B;
    int tid = threadIdx.x, lane = tid & 31, wid = tid >> 5;
    int bx = blockIdx.x;
    int oT = bx & 3, lT = (bx >> 2) & 15, b = bx >> 6;
    int wm = (wid & 3) * 32, wn = (wid >> 2) * 64;

    const char* wb = (const char*)g_W;
    const char* bb = (const char*)g_Bx;

    // ka as half2 (broadcast)
    __half2 kh[KW];
#pragma unroll
    for (int k = 0; k < KW; ++k) {
        float kv = g_ka[b * KW + k];
        kh[k] = __floats2half2_rn(kv, kv);
    }

    // A tile j = ic*5 + kw
    auto issueA = [&](int j) {
        int ic = j / 5, kw = j - ic * 5;
        const char* sA = wb + (size_t)((kw * 4 + oT) * 8 + ic) * TILE_B;
        uint32_t dA = sbase + (j % 3) * TILE_B;
#pragma unroll
        for (int q = 0; q < 2; ++q) {
            int c = (tid + q * 512) * 16;
            cp16(dA + c, sA + c);
        }
    };
    // B slab for ic: rows [lT*256, lT*256+264)
    auto issueB = [&](int icn) {
        const char* sB = bb + ((size_t)(b * 8 + icn) * BROWS + (size_t)lT * 256) * 128;
        uint32_t dB = bbase + (icn & 1) * BBUF;
        for (int c = tid; c < BBUF / 16; c += 512)
            cp16(dB + c * 16, sB + c * 16);
    };

    float acc[2][8][4];
#pragma unroll
    for (int mi = 0; mi < 2; ++mi)
#pragma unroll
        for (int ni = 0; ni < 8; ++ni)
#pragma unroll
            for (int r = 0; r < 4; ++r) acc[mi][ni][r] = 0.f;

    int rowA = (lane & 7) + 8 * ((lane >> 3) & 1);
    int colA = (lane >> 4) * 16;
    uint32_t axor = (uint32_t)((lane & 7) << 4);
    // B ldmx4: lanes -> (n-subtile, k-half)
    int nOffB = ((lane >> 4) & 1) * 8 + (lane & 7);
    int colB = ((lane >> 3) & 1) * 16;

    issueA(0); issueB(0); cp_commit();
    issueA(1); issueB(1); cp_commit();

#pragma unroll 1
    for (int it = 0; it < NIT; ++it) {
        int ic = it / 5, kw = it - ic * 5;
        int j2 = it + 2;
        if (j2 < NIT) issueA(j2);
        if (kw == 1 && ic >= 1 && ic < 7) issueB(ic + 1);
        cp_commit();
        cp_wait<2>();
        __syncthreads();

        // scale A stage by ka[kw] in-place (half2)
        uint32_t sA = sbase + (it % 3) * TILE_B;
        {
            uint4* p = (uint4*)(sm + (sA - sbase) + tid * 32);
            __half2 kk = kh[kw];
#pragma unroll
            for (int q = 0; q < 2; ++q) {
                uint4 v = p[q];
                __half2* h = (__half2*)&v;
                h[0] = __hmul2(h[0], kk); h[1] = __hmul2(h[1], kk);
                h[2] = __hmul2(h[2], kk); h[3] = __hmul2(h[3], kk);
                p[q] = v;
            }
        }
        __syncthreads();

        uint32_t sB = bbase + (ic & 1) * BBUF;
#pragma unroll
        for (int ks = 0; ks < 4; ++ks) {
            uint32_t afr[2][4], bfr[4][4];
#pragma unroll
            for (int mi = 0; mi < 2; ++mi) {
                uint32_t ar = (uint32_t)(wm + mi * 16 + rowA);
                ldmx4(afr[mi][0], afr[mi][1], afr[mi][2], afr[mi][3],
                      (sA + ar * 128 + ks * 32 + colA) ^ axor);
            }
#pragma unroll
            for (int nb = 0; nb < 4; ++nb) {
                uint32_t br = (uint32_t)(kw + wn + nb * 16 + nOffB);
                uint32_t bxor = (br & 7) << 4;
                ldmx4(bfr[nb][0], bfr[nb][1], bfr[nb][2], bfr[nb][3],
                      (sB + br * 128 + ks * 32 + colB) ^ bxor);
            }
#pragma unroll
            for (int mi = 0; mi < 2; ++mi)
#pragma unroll
                for (int nb = 0; nb < 4; ++nb) {
                    mma16816(acc[mi][nb * 2],     afr[mi], &bfr[nb][0]);
                    mma16816(acc[mi][nb * 2 + 1], afr[mi], &bfr[nb][2]);
                }
        }
        __syncthreads();
    }

    // epilogue: scale*acc + bias
    int r0 = wm + (lane >> 2);
    float scb[2][2], bib[2][2];
#pragma unroll
    for (int mi = 0; mi < 2; ++mi) {
        int o0 = oT * 128 + r0 + mi * 16;
        scb[mi][0] = g_scale[b * CO + o0];
        scb[mi][1] = g_scale[b * CO + o0 + 8];
        bib[mi][0] = bias[o0];
        bib[mi][1] = bias[o0 + 8];
    }
    float* ob = out + ((size_t)(b * CO + oT * 128)) * LL + lT * 256;
#pragma unroll
    for (int mi = 0; mi < 2; ++mi) {
#pragma unroll
        for (int ni = 0; ni < 8; ++ni) {
            int rr = r0 + mi * 16;
            int cc = wn + ni * 8 + (lane & 3) * 2;
            float2 v0 = make_float2(scb[mi][0] * acc[mi][ni][0] + bib[mi][0],
                                    scb[mi][0] * acc[mi][ni][1] + bib[mi][0]);
            float2 v1 = make_float2(scb[mi][1] * acc[mi][ni][2] + bib[mi][1],
                                    scb[mi][1] * acc[mi][ni][3] + bib[mi][1]);
            *(float2*)(ob + (size_t)rr * LL + cc) = v0;
            *(float2*)(ob + (size_t)(rr + 8) * LL + cc) = v1;
        }
    }
}

// ---------------- launch ----------------
extern "C" void kernel_launch(void* const* d_in, const int* in_sizes, int n_in,
                              void* d_out, int out_size) {
    const float* x      = (const float*)d_in[0];
    const float* weight = (const float*)d_in[1];
    const float* bias   = (const float*)d_in[2];
    const float* ka_w1 = (const float*)d_in[3],  *ka_b1 = (const float*)d_in[4];
    const float* ka_w2 = (const float*)d_in[5],  *ka_b2 = (const float*)d_in[6];
    const float* sa_w1 = (const float*)d_in[7],  *sa_b1 = (const float*)d_in[8];
    const float* sa_w2 = (const float*)d_in[9],  *sa_b2 = (const float*)d_in[10];
    const float* ia_w1 = (const float*)d_in[11], *ia_b1 = (const float*)d_in[12];
    const float* ia_w2 = (const float*)d_in[13], *ia_b2 = (const float*)d_in[14];
    const float* oa_w1 = (const float*)d_in[15], *oa_b1 = (const float*)d_in[16];
    const float* oa_w2 = (const float*)d_in[17], *oa_b2 = (const float*)d_in[18];
    float* out = (float*)d_out;

    cudaFuncSetAttribute(k_gemm, cudaFuncAttributeMaxDynamicSharedMemorySize, GEMM_SMEM);

    k_avg<<<BB * CI, 256>>>(x);
    k_att<<<BB, 512>>>(ka_w1, ka_b1, ka_w2, ka_b2,
                       sa_w1, sa_b1, sa_w2, sa_b2,
                       ia_w1, ia_b1, ia_w2, ia_b2,
                       oa_w1, oa_b1, oa_w2, oa_b2);
    k_prepW<<<KW * 4 * 8, 128>>>(weight);
    k_prepB<<<BB * 8 * 33, 256>>>(x);
    k_gemm<<<BB * 16 * 4, 512, GEMM_SMEM>>>(bias, out);
}

// round 6
// speedup vs baseline: 1.0007x; 1.0007x over previous
#include <cuda_runtime.h>
#include <cuda_fp16.h>
#include <cstdint>
#include <cstddef>

#define DI __device__ __forceinline__

// ---------------- problem constants ----------------
constexpr int BB = 8, CI = 512, CO = 512, KW = 5, LL = 4096;

// ---------------- GEMM tiling ----------------
constexpr int NIT = 40;                      // ic(8) x kw(5)
constexpr int TILE_B = 16384;                // A tile: 128 rows x 128B
constexpr int BROWSBUF = 264;                // B slab rows per ic
constexpr int BBUF = BROWSBUF * 128;         // 33792 B
constexpr int ASTAGE = 3;
constexpr int GEMM_SMEM = ASTAGE * TILE_B + 2 * BBUF;   // 116736

constexpr int BROWS = 4224;                  // g_Bx rows (33*128)

// ---------------- device scratch ----------------
// x rows: [b][ic(8)][gl(4224)] x 64 halfs (128B rows), swizzle phase = gl&7; l = gl-2
__device__ __half g_Bx[(size_t)BB * 8 * BROWS * 64];
// weight tiles (batch-independent): [k][oT(4)][ic(8)], 128x128B swizzled tiles
__device__ __half g_W[(size_t)KW * 4 * 8 * 8192];
__device__ float  g_avg[BB * CI];
__device__ float  g_ka[BB * KW];
__device__ float  g_scale[BB * CO];

// ---------------- helpers ----------------
DI uint32_t smem_u32(const void* p) {
    uint32_t a;
    asm("{ .reg .u64 t; cvta.to.shared.u64 t, %1; cvt.u32.u64 %0, t; }" : "=r"(a) : "l"(p));
    return a;
}
DI uint32_t swz(uint32_t off) { return off ^ ((off >> 3) & 0x70); }
DI void cp16(uint32_t dst, const void* src) {
    asm volatile("cp.async.cg.shared.global [%0], [%1], 16;" :: "r"(dst), "l"(src) : "memory");
}
DI void cp_commit() { asm volatile("cp.async.commit_group;" ::: "memory"); }
template <int N> DI void cp_wait() { asm volatile("cp.async.wait_group %0;" :: "n"(N) : "memory"); }

DI void ldmx4(uint32_t& r0, uint32_t& r1, uint32_t& r2, uint32_t& r3, uint32_t a) {
    asm volatile("ldmatrix.sync.aligned.m8n8.x4.shared.b16 {%0,%1,%2,%3}, [%4];"
                 : "=r"(r0), "=r"(r1), "=r"(r2), "=r"(r3) : "r"(a));
}
DI void mma16816(float* c, const uint32_t* a, const uint32_t* b) {
    asm volatile(
        "mma.sync.aligned.m16n8k16.row.col.f32.f16.f16.f32 "
        "{%0,%1,%2,%3}, {%4,%5,%6,%7}, {%8,%9}, {%0,%1,%2,%3};"
        : "+f"(c[0]), "+f"(c[1]), "+f"(c[2]), "+f"(c[3])
        : "r"(a[0]), "r"(a[1]), "r"(a[2]), "r"(a[3]), "r"(b[0]), "r"(b[1]));
}

// ---------------- kernel 1: per-(b,c) mean over L ----------------
__global__ void k_avg(const float* __restrict__ x) {
    int row = blockIdx.x;
    const float4* p = (const float4*)(x + (size_t)row * LL);
    float s = 0.f;
#pragma unroll
    for (int q = 0; q < 4; ++q) {
        float4 v = p[threadIdx.x + q * 256];
        s += (v.x + v.y) + (v.z + v.w);
    }
#pragma unroll
    for (int o = 16; o; o >>= 1) s += __shfl_xor_sync(0xFFFFFFFFu, s, o);
    __shared__ float ws[8];
    if ((threadIdx.x & 31) == 0) ws[threadIdx.x >> 5] = s;
    __syncthreads();
    if (threadIdx.x == 0) {
        float t = 0.f;
#pragma unroll
        for (int w = 0; w < 8; ++w) t += ws[w];
        g_avg[row] = t * (1.f / (float)LL);
    }
}

// ---------------- kernel 2: attention branches ----------------
__global__ void k_att(
    const float* ka_w1, const float* ka_b1, const float* ka_w2, const float* ka_b2,
    const float* sa_w1, const float* sa_b1, const float* sa_w2, const float* sa_b2,
    const float* ia_w1, const float* ia_b1, const float* ia_w2, const float* ia_b2,
    const float* oa_w1, const float* oa_b1, const float* oa_w2, const float* oa_b2) {
    __shared__ float avgs[CI];
    __shared__ float h[4][128];
    __shared__ float sav;
    int b = blockIdx.x, t = threadIdx.x;   // 512 threads
    avgs[t] = g_avg[b * CI + t];
    __syncthreads();

    int br = t >> 7, row = t & 127;
    const float* w1 = br == 0 ? ka_w1 : br == 1 ? sa_w1 : br == 2 ? ia_w1 : oa_w1;
    const float* b1 = br == 0 ? ka_b1 : br == 1 ? sa_b1 : br == 2 ? ia_b1 : oa_b1;
    float s = b1[row];
    const float* wr = w1 + (size_t)row * CI;
#pragma unroll 8
    for (int u = 0; u < CI; ++u) s += avgs[u] * wr[u];
    h[br][row] = fmaxf(s, 0.f);
    __syncthreads();

    float s2 = oa_b2[t];
    const float* w2r = oa_w2 + (size_t)t * 128;
#pragma unroll 8
    for (int r = 0; r < 128; ++r) s2 += h[3][r] * w2r[r];
    float oav = 1.f / (1.f + expf(-s2));

    float s3 = ia_b2[t];
    const float* w3r = ia_w2 + (size_t)t * 128;
#pragma unroll 8
    for (int r = 0; r < 128; ++r) s3 += h[2][r] * w3r[r];
    float iav = 1.f / (1.f + expf(-s3));

    if (t < KW) {
        float s4 = ka_b2[t];
        const float* w4r = ka_w2 + (size_t)t * 128;
#pragma unroll 8
        for (int r = 0; r < 128; ++r) s4 += h[0][r] * w4r[r];
        g_ka[b * KW + t] = 1.f / (1.f + expf(-s4));
    }
    if (t == 256) {
        float s5 = sa_b2[0];
#pragma unroll 8
        for (int r = 0; r < 128; ++r) s5 += h[1][r] * sa_w2[r];
        sav = 1.f / (1.f + expf(-s5));
    }
    __syncthreads();
    g_scale[b * CO + t] = sav * iav * oav;
}

// ---------------- kernel 3: weight -> fp16 swizzled tiles (no ka) ----------------
__global__ void k_prepW(const float* __restrict__ w) {
    int bx = blockIdx.x;                 // k*32 + oT*8 + ic, 160 blocks
    int k = bx >> 5, oT = (bx >> 3) & 3, ic = bx & 7;
    int o = oT * 128 + threadIdx.x;      // 128 threads = rows
    char* tile = (char*)g_W + (size_t)bx * TILE_B;
    const float* wr = w + ((size_t)o * CI + ic * 64) * KW + k;
#pragma unroll 8
    for (int j = 0; j < 32; ++j) {
        float v0 = wr[(size_t)(2 * j) * KW];
        float v1 = wr[(size_t)(2 * j + 1) * KW];
        __half2 hv = __floats2half2_rn(v0, v1);
        *(uint32_t*)(tile + swz((uint32_t)threadIdx.x * 128 + j * 4)) = *(uint32_t*)&hv;
    }
}

// ---------------- kernel 4: x rows -> fp16, transposed, global-phase swizzled ----
__global__ void k_prepB(const float* __restrict__ x) {
    __shared__ float xs[128][65];        // [row offset][channel]
    int bx = blockIdx.x;                 // b*(8*33) + ic*33 + g
    int g = bx % 33;
    int ic = (bx / 33) & 7;
    int b = bx / (33 * 8);
    int tid = threadIdx.x;               // 256 threads
    for (int e = tid; e < 64 * 128; e += 256) {
        int c = e >> 7, off = e & 127;
        int l = g * 128 - 2 + off;
        float v = 0.f;
        if (l >= 0 && l < LL)
            v = x[((size_t)(b * CI + ic * 64 + c)) * LL + l];
        xs[off][c] = v;
    }
    __syncthreads();
    char* base = (char*)g_Bx + ((size_t)(b * 8 + ic) * BROWS + (size_t)g * 128) * 128;
#pragma unroll
    for (int q = 0; q < 4; ++q) {
        int idx = tid + q * 256;         // 1024: 128 rows x 8 chunks
        int r = idx >> 3, j = idx & 7;
        uint32_t u[4];
#pragma unroll
        for (int p = 0; p < 4; ++p) {
            __half2 hv = __floats2half2_rn(xs[r][j * 8 + 2 * p], xs[r][j * 8 + 2 * p + 1]);
            u[p] = *(uint32_t*)&hv;
        }
        uint32_t off = (uint32_t)(j * 16) ^ (uint32_t)((r & 7) * 16);
        *(uint4*)(base + (size_t)r * 128 + off) = make_uint4(u[0], u[1], u[2], u[3]);
    }
}

// ---------------- kernel 5: HMMA GEMM (BM128 x BN256), B slab reuse ----------------
__global__ void __launch_bounds__(512, 1)
k_gemm(const float* __restrict__ bias, float* __restrict__ out) {
    extern __shared__ char sm[];
    uint32_t sbase = smem_u32(sm);
    uint32_t bbase = sbase + ASTAGE * TILE_B;
    int tid = threadIdx.x, lane = tid & 31, wid = tid >> 5;
    int bx = blockIdx.x;
    int oT = bx & 3, lT = (bx >> 2) & 15, b = bx >> 6;
    int wm = (wid & 3) * 32, wn = (wid >> 2) * 64;

    const char* wb = (const char*)g_W;
    const char* bb = (const char*)g_Bx;

    // ka as half2 (broadcast)
    __half2 kh[KW];
#pragma unroll
    for (int k = 0; k < KW; ++k) {
        float kv = g_ka[b * KW + k];
        kh[k] = __floats2half2_rn(kv, kv);
    }

    // A tile j = ic*5 + kw
    auto issueA = [&](int j) {
        int ic = j / 5, kw = j - ic * 5;
        const char* sA = wb + (size_t)((kw * 4 + oT) * 8 + ic) * TILE_B;
        uint32_t dA = sbase + (j % 3) * TILE_B;
#pragma unroll
        for (int q = 0; q < 2; ++q) {
            int c = (tid + q * 512) * 16;
            cp16(dA + c, sA + c);
        }
    };
    // B slab for ic: rows [lT*256, lT*256+264)
    auto issueB = [&](int icn) {
        const char* sB = bb + ((size_t)(b * 8 + icn) * BROWS + (size_t)lT * 256) * 128;
        uint32_t dB = bbase + (icn & 1) * BBUF;
        for (int c = tid; c < BBUF / 16; c += 512)
            cp16(dB + c * 16, sB + c * 16);
    };

    float acc[2][8][4];
#pragma unroll
    for (int mi = 0; mi < 2; ++mi)
#pragma unroll
        for (int ni = 0; ni < 8; ++ni)
#pragma unroll
            for (int r = 0; r < 4; ++r) acc[mi][ni][r] = 0.f;

    int rowA = (lane & 7) + 8 * ((lane >> 3) & 1);
    int colA = (lane >> 4) * 16;
    uint32_t axor = (uint32_t)((lane & 7) << 4);
    // B ldmx4: lanes -> (n-subtile, k-half)
    int nOffB = ((lane >> 4) & 1) * 8 + (lane & 7);
    int colB = ((lane >> 3) & 1) * 16;

    issueA(0); issueB(0); cp_commit();
    issueA(1); issueB(1); cp_commit();

#pragma unroll 1
    for (int it = 0; it < NIT; ++it) {
        int ic = it / 5, kw = it - ic * 5;
        int j2 = it + 2;
        if (j2 < NIT) issueA(j2);
        if (kw == 1 && ic >= 1 && ic < 7) issueB(ic + 1);
        cp_commit();
        cp_wait<2>();
        __syncthreads();

        // scale A stage by ka[kw] in-place (half2)
        uint32_t sA = sbase + (it % 3) * TILE_B;
        {
            uint4* p = (uint4*)(sm + (sA - sbase) + tid * 32);
            __half2 kk = kh[kw];
#pragma unroll
            for (int q = 0; q < 2; ++q) {
                uint4 v = p[q];
                __half2* h = (__half2*)&v;
                h[0] = __hmul2(h[0], kk); h[1] = __hmul2(h[1], kk);
                h[2] = __hmul2(h[2], kk); h[3] = __hmul2(h[3], kk);
                p[q] = v;
            }
        }
        __syncthreads();

        uint32_t sB = bbase + (ic & 1) * BBUF;
#pragma unroll
        for (int ks = 0; ks < 4; ++ks) {
            uint32_t afr[2][4], bfr[4][4];
#pragma unroll
            for (int mi = 0; mi < 2; ++mi) {
                uint32_t ar = (uint32_t)(wm + mi * 16 + rowA);
                ldmx4(afr[mi][0], afr[mi][1], afr[mi][2], afr[mi][3],
                      (sA + ar * 128 + ks * 32 + colA) ^ axor);
            }
#pragma unroll
            for (int nb = 0; nb < 4; ++nb) {
                uint32_t br = (uint32_t)(kw + wn + nb * 16 + nOffB);
                uint32_t bxor = (br & 7) << 4;
                ldmx4(bfr[nb][0], bfr[nb][1], bfr[nb][2], bfr[nb][3],
                      (sB + br * 128 + ks * 32 + colB) ^ bxor);
            }
#pragma unroll
            for (int mi = 0; mi < 2; ++mi)
#pragma unroll
                for (int nb = 0; nb < 4; ++nb) {
                    mma16816(acc[mi][nb * 2],     afr[mi], &bfr[nb][0]);
                    mma16816(acc[mi][nb * 2 + 1], afr[mi], &bfr[nb][2]);
                }
        }
        __syncthreads();
    }

    // epilogue: scale*acc + bias
    int r0 = wm + (lane >> 2);
    float scb[2][2], bib[2][2];
#pragma unroll
    for (int mi = 0; mi < 2; ++mi) {
        int o0 = oT * 128 + r0 + mi * 16;
        scb[mi][0] = g_scale[b * CO + o0];
        scb[mi][1] = g_scale[b * CO + o0 + 8];
        bib[mi][0] = bias[o0];
        bib[mi][1] = bias[o0 + 8];
    }
    float* ob = out + ((size_t)(b * CO + oT * 128)) * LL + lT * 256;
#pragma unroll
    for (int mi = 0; mi < 2; ++mi) {
#pragma unroll
        for (int ni = 0; ni < 8; ++ni) {
            int rr = r0 + mi * 16;
            int cc = wn + ni * 8 + (lane & 3) * 2;
            float2 v0 = make_float2(scb[mi][0] * acc[mi][ni][0] + bib[mi][0],
                                    scb[mi][0] * acc[mi][ni][1] + bib[mi][0]);
            float2 v1 = make_float2(scb[mi][1] * acc[mi][ni][2] + bib[mi][1],
                                    scb[mi][1] * acc[mi][ni][3] + bib[mi][1]);
            *(float2*)(ob + (size_t)rr * LL + cc) = v0;
            *(float2*)(ob + (size_t)(rr + 8) * LL + cc) = v1;
        }
    }
}

// ---------------- launch ----------------
extern "C" void kernel_launch(void* const* d_in, const int* in_sizes, int n_in,
                              void* d_out, int out_size) {
    const float* x      = (const float*)d_in[0];
    const float* weight = (const float*)d_in[1];
    const float* bias   = (const float*)d_in[2];
    const float* ka_w1 = (const float*)d_in[3],  *ka_b1 = (const float*)d_in[4];
    const float* ka_w2 = (const float*)d_in[5],  *ka_b2 = (const float*)d_in[6];
    const float* sa_w1 = (const float*)d_in[7],  *sa_b1 = (const float*)d_in[8];
    const float* sa_w2 = (const float*)d_in[9],  *sa_b2 = (const float*)d_in[10];
    const float* ia_w1 = (const float*)d_in[11], *ia_b1 = (const float*)d_in[12];
    const float* ia_w2 = (const float*)d_in[13], *ia_b2 = (const float*)d_in[14];
    const float* oa_w1 = (const float*)d_in[15], *oa_b1 = (const float*)d_in[16];
    const float* oa_w2 = (const float*)d_in[17], *oa_b2 = (const float*)d_in[18];
    float* out = (float*)d_out;

    cudaFuncSetAttribute(k_gemm, cudaFuncAttributeMaxDynamicSharedMemorySize, GEMM_SMEM);

    k_avg<<<BB * CI, 256>>>(x);
    k_att<<<BB, 512>>>(ka_w1, ka_b1, ka_w2, ka_b2,
                       sa_w1, sa_b1, sa_w2, sa_b2,
                       ia_w1, ia_b1, ia_w2, ia_b2,
                       oa_w1, oa_b1, oa_w2, oa_b2);
    k_prepW<<<KW * 4 * 8, 128>>>(weight);
    k_prepB<<<BB * 8 * 33, 256>>>(x);
    k_gemm<<<BB * 16 * 4, 512, GEMM_SMEM>>>(bias, out);
}

// round 7
// speedup vs baseline: 1.1638x; 1.1630x over previous
#include <cuda_runtime.h>
#include <cuda_fp16.h>
#include <cstdint>
#include <cstddef>

#define DI __device__ __forceinline__

// ---------------- problem constants ----------------
constexpr int BB = 8, CI = 512, CO = 512, KW = 5, LL = 4096;

// ---------------- GEMM tiling ----------------
constexpr int NIT = 40;                      // kw(5) outer x ic(8) inner
constexpr int TILE_B = 16384;                // 128 rows x 128B
constexpr int STAGE_B = 2 * TILE_B;          // 32 KB (A + B)
constexpr int NSTAGE = 3;
constexpr int GEMM_SMEM = NSTAGE * STAGE_B;  // 96 KB

constexpr int BROWS = 4224;                  // g_Bx rows (33*128)

// ---------------- device scratch ----------------
// x rows: [b][ic(8)][gl(4224)] x 64 halfs (128B rows), swizzle phase = gl&7; l = gl-2
__device__ __half g_Bx[(size_t)BB * 8 * BROWS * 64];
// weight tiles (batch-independent): [k][oT(4)][ic(8)], 128x128B swizzled tiles
__device__ __half g_W[(size_t)KW * 4 * 8 * 8192];
__device__ float  g_avg[BB * CI];
__device__ float  g_ka[BB * KW];
__device__ float  g_scale[BB * CO];

// ---------------- helpers ----------------
DI uint32_t smem_u32(const void* p) {
    uint32_t a;
    asm("{ .reg .u64 t; cvta.to.shared.u64 t, %1; cvt.u32.u64 %0, t; }" : "=r"(a) : "l"(p));
    return a;
}
DI uint32_t swz(uint32_t off) { return off ^ ((off >> 3) & 0x70); }
DI void cp16(uint32_t dst, const void* src) {
    asm volatile("cp.async.cg.shared.global [%0], [%1], 16;" :: "r"(dst), "l"(src) : "memory");
}
DI void cp_commit() { asm volatile("cp.async.commit_group;" ::: "memory"); }
template <int N> DI void cp_wait() { asm volatile("cp.async.wait_group %0;" :: "n"(N) : "memory"); }

DI void ldmx4(uint32_t& r0, uint32_t& r1, uint32_t& r2, uint32_t& r3, uint32_t a) {
    asm volatile("ldmatrix.sync.aligned.m8n8.x4.shared.b16 {%0,%1,%2,%3}, [%4];"
                 : "=r"(r0), "=r"(r1), "=r"(r2), "=r"(r3) : "r"(a));
}
DI void ldmx2(uint32_t& r0, uint32_t& r1, uint32_t a) {
    asm volatile("ldmatrix.sync.aligned.m8n8.x2.shared.b16 {%0,%1}, [%2];"
                 : "=r"(r0), "=r"(r1) : "r"(a));
}
DI void mma16816(float* c, const uint32_t* a, const uint32_t* b) {
    asm volatile(
        "mma.sync.aligned.m16n8k16.row.col.f32.f16.f16.f32 "
        "{%0,%1,%2,%3}, {%4,%5,%6,%7}, {%8,%9}, {%0,%1,%2,%3};"
        : "+f"(c[0]), "+f"(c[1]), "+f"(c[2]), "+f"(c[3])
        : "r"(a[0]), "r"(a[1]), "r"(a[2]), "r"(a[3]), "r"(b[0]), "r"(b[1]));
}

// ---------------- kernel 1: weight -> fp16 swizzled tiles + zero g_avg ----------------
__global__ void k_prepW(const float* __restrict__ w) {
    int bx = blockIdx.x;                 // k*32 + oT*8 + ic, 160 blocks
    if (bx < 32) g_avg[bx * 128 + threadIdx.x] = 0.f;   // zero before prepB atomics
    int k = bx >> 5, oT = (bx >> 3) & 3, ic = bx & 7;
    int o = oT * 128 + threadIdx.x;      // 128 threads = rows
    char* tile = (char*)g_W + (size_t)bx * TILE_B;
    const float* wr = w + ((size_t)o * CI + ic * 64) * KW + k;
#pragma unroll 8
    for (int j = 0; j < 32; ++j) {
        float v0 = wr[(size_t)(2 * j) * KW];
        float v1 = wr[(size_t)(2 * j + 1) * KW];
        __half2 hv = __floats2half2_rn(v0, v1);
        *(uint32_t*)(tile + swz((uint32_t)threadIdx.x * 128 + j * 4)) = *(uint32_t*)&hv;
    }
}

// ---------------- kernel 2: x -> fp16 transposed swizzled rows + fused mean ----------
__global__ void k_prepB(const float* __restrict__ x) {
    __shared__ float xs[128][65];        // [row offset][channel]
    int bx = blockIdx.x;                 // b*(8*33) + ic*33 + g
    int g = bx % 33;
    int ic = (bx / 33) & 7;
    int b = bx / (33 * 8);
    int tid = threadIdx.x;               // 256 threads
    for (int e = tid; e < 64 * 128; e += 256) {
        int c = e >> 7, off = e & 127;
        int l = g * 128 - 2 + off;
        float v = 0.f;
        if (l >= 0 && l < LL)
            v = x[((size_t)(b * CI + ic * 64 + c)) * LL + l];
        xs[off][c] = v;
    }
    __syncthreads();

    // fused avg: blocks are disjoint in l (each l appears in exactly one (g,off))
    {
        int c = tid >> 2, part = tid & 3;   // 4 threads per channel
        float s = 0.f;
#pragma unroll
        for (int q = 0; q < 32; ++q) s += xs[part * 32 + q][c];
        s += __shfl_xor_sync(0xFFFFFFFFu, s, 1);
        s += __shfl_xor_sync(0xFFFFFFFFu, s, 2);
        if (part == 0)
            atomicAdd(&g_avg[b * CI + ic * 64 + c], s * (1.f / (float)LL));
    }

    char* base = (char*)g_Bx + ((size_t)(b * 8 + ic) * BROWS + (size_t)g * 128) * 128;
#pragma unroll
    for (int q = 0; q < 4; ++q) {
        int idx = tid + q * 256;         // 1024: 128 rows x 8 chunks
        int r = idx >> 3, j = idx & 7;
        uint32_t u[4];
#pragma unroll
        for (int p = 0; p < 4; ++p) {
            __half2 hv = __floats2half2_rn(xs[r][j * 8 + 2 * p], xs[r][j * 8 + 2 * p + 1]);
            u[p] = *(uint32_t*)&hv;
        }
        uint32_t off = (uint32_t)(j * 16) ^ (uint32_t)((r & 7) * 16);
        *(uint4*)(base + (size_t)r * 128 + off) = make_uint4(u[0], u[1], u[2], u[3]);
    }
}

// ---------------- kernel 3: attention branches ----------------
__global__ void k_att(
    const float* ka_w1, const float* ka_b1, const float* ka_w2, const float* ka_b2,
    const float* sa_w1, const float* sa_b1, const float* sa_w2, const float* sa_b2,
    const float* ia_w1, const float* ia_b1, const float* ia_w2, const float* ia_b2,
    const float* oa_w1, const float* oa_b1, const float* oa_w2, const float* oa_b2) {
    __shared__ float avgs[CI];
    __shared__ float h[4][128];
    __shared__ float sav;
    int b = blockIdx.x, t = threadIdx.x;   // 512 threads
    avgs[t] = g_avg[b * CI + t];
    __syncthreads();

    int br = t >> 7, row = t & 127;
    const float* w1 = br == 0 ? ka_w1 : br == 1 ? sa_w1 : br == 2 ? ia_w1 : oa_w1;
    const float* b1 = br == 0 ? ka_b1 : br == 1 ? sa_b1 : br == 2 ? ia_b1 : oa_b1;
    float s = b1[row];
    const float* wr = w1 + (size_t)row * CI;
#pragma unroll 8
    for (int u = 0; u < CI; ++u) s += avgs[u] * wr[u];
    h[br][row] = fmaxf(s, 0.f);
    __syncthreads();

    float s2 = oa_b2[t];
    const float* w2r = oa_w2 + (size_t)t * 128;
#pragma unroll 8
    for (int r = 0; r < 128; ++r) s2 += h[3][r] * w2r[r];
    float oav = 1.f / (1.f + expf(-s2));

    float s3 = ia_b2[t];
    const float* w3r = ia_w2 + (size_t)t * 128;
#pragma unroll 8
    for (int r = 0; r < 128; ++r) s3 += h[2][r] * w3r[r];
    float iav = 1.f / (1.f + expf(-s3));

    if (t < KW) {
        float s4 = ka_b2[t];
        const float* w4r = ka_w2 + (size_t)t * 128;
#pragma unroll 8
        for (int r = 0; r < 128; ++r) s4 += h[0][r] * w4r[r];
        g_ka[b * KW + t] = 1.f / (1.f + expf(-s4));
    }
    if (t == 256) {
        float s5 = sa_b2[0];
#pragma unroll 8
        for (int r = 0; r < 128; ++r) s5 += h[1][r] * sa_w2[r];
        sav = 1.f / (1.f + expf(-s5));
    }
    __syncthreads();
    g_scale[b * CO + t] = sav * iav * oav;
}

// ---------------- kernel 4: HMMA GEMM (BM128 x BN128), ka folded in B frags ----------
__global__ void __launch_bounds__(256, 2)
k_gemm(const float* __restrict__ bias, float* __restrict__ out) {
    extern __shared__ char sm[];
    uint32_t sbase = smem_u32(sm);
    int tid = threadIdx.x, lane = tid & 31, wid = tid >> 5;
    int bx = blockIdx.x;
    int oT = bx & 3, lT = (bx >> 2) & 31, b = bx >> 7;
    int wm = (wid & 1) * 64, wn = (wid >> 1) * 32;

    const char* wb = (const char*)g_W;
    const char* bb = (const char*)g_Bx;

    __half2 kh[KW];
#pragma unroll
    for (int k = 0; k < KW; ++k) {
        float kv = g_ka[b * KW + k];
        kh[k] = __floats2half2_rn(kv, kv);
    }

    // iteration j: kw = j>>3 (outer), ic = j&7 (inner)
    auto issue = [&](int j, int s) {
        int kw = j >> 3, ic = j & 7;
        const char* sA = wb + (size_t)((kw * 4 + oT) * 8 + ic) * TILE_B;
        const char* sB = bb + ((size_t)(b * 8 + ic) * BROWS + (size_t)(lT * 128 + kw)) * 128;
        uint32_t dA = sbase + s * STAGE_B;
        uint32_t dB = dA + TILE_B;
#pragma unroll
        for (int q = 0; q < 4; ++q) {
            int c = (tid + q * 256) * 16;
            cp16(dA + c, sA + c);
        }
#pragma unroll
        for (int q = 0; q < 4; ++q) {
            int c = (tid + q * 256) * 16;
            cp16(dB + c, sB + c);
        }
    };

    float acc[4][4][4];
#pragma unroll
    for (int mi = 0; mi < 4; ++mi)
#pragma unroll
        for (int ni = 0; ni < 4; ++ni)
#pragma unroll
            for (int r = 0; r < 4; ++r) acc[mi][ni][r] = 0.f;

    int rowA = (lane & 7) + 8 * ((lane >> 3) & 1);
    int colA = (lane >> 4) * 16;
    uint32_t axor = (uint32_t)((lane & 7) << 4);
    int rowB = lane & 7;
    int colB = ((lane >> 3) & 1) * 16;

    issue(0, 0); cp_commit();
    issue(1, 1); cp_commit();

#pragma unroll 1
    for (int it = 0; it < NIT; ++it) {
        cp_wait<1>();
        __syncthreads();                        // everyone done reading stage (it-1)%3

        int j2 = it + 2;
        if (j2 < NIT) issue(j2, j2 % 3);        // writes stage (it+2)%3 == (it-1)%3
        cp_commit();

        int kw = it >> 3;
        uint32_t bxor = (uint32_t)(((rowB + kw) & 7) << 4);
        __half2 kk = kh[kw];
        uint32_t sA = sbase + (it % 3) * STAGE_B;
        uint32_t sB = sA + TILE_B;
#pragma unroll
        for (int ks = 0; ks < 4; ++ks) {
            uint32_t afr[4][4], bfr[4][2];
#pragma unroll
            for (int mi = 0; mi < 4; ++mi)
                ldmx4(afr[mi][0], afr[mi][1], afr[mi][2], afr[mi][3],
                      (sA + (uint32_t)(wm + mi * 16 + rowA) * 128 + ks * 32 + colA) ^ axor);
#pragma unroll
            for (int ni = 0; ni < 4; ++ni) {
                ldmx2(bfr[ni][0], bfr[ni][1],
                      (sB + (uint32_t)(wn + ni * 8 + rowB) * 128 + ks * 32 + colB) ^ bxor);
                *(__half2*)&bfr[ni][0] = __hmul2(*(__half2*)&bfr[ni][0], kk);
                *(__half2*)&bfr[ni][1] = __hmul2(*(__half2*)&bfr[ni][1], kk);
            }
#pragma unroll
            for (int mi = 0; mi < 4; ++mi)
#pragma unroll
                for (int ni = 0; ni < 4; ++ni)
                    mma16816(acc[mi][ni], afr[mi], bfr[ni]);
        }
    }

    // epilogue: scale*acc + bias
    int r0 = wm + (lane >> 2);
    float scb[4][2], bib[4][2];
#pragma unroll
    for (int mi = 0; mi < 4; ++mi) {
        int o0 = oT * 128 + r0 + mi * 16;
        scb[mi][0] = g_scale[b * CO + o0];
        scb[mi][1] = g_scale[b * CO + o0 + 8];
        bib[mi][0] = bias[o0];
        bib[mi][1] = bias[o0 + 8];
    }
    float* ob = out + ((size_t)(b * CO + oT * 128)) * LL + lT * 128;
#pragma unroll
    for (int mi = 0; mi < 4; ++mi) {
#pragma unroll
        for (int ni = 0; ni < 4; ++ni) {
            int rr = r0 + mi * 16;
            int cc = wn + ni * 8 + (lane & 3) * 2;
            float2 v0 = make_float2(scb[mi][0] * acc[mi][ni][0] + bib[mi][0],
                                    scb[mi][0] * acc[mi][ni][1] + bib[mi][0]);
            float2 v1 = make_float2(scb[mi][1] * acc[mi][ni][2] + bib[mi][1],
                                    scb[mi][1] * acc[mi][ni][3] + bib[mi][1]);
            *(float2*)(ob + (size_t)rr * LL + cc) = v0;
            *(float2*)(ob + (size_t)(rr + 8) * LL + cc) = v1;
        }
    }
}

// ---------------- launch ----------------
extern "C" void kernel_launch(void* const* d_in, const int* in_sizes, int n_in,
                              void* d_out, int out_size) {
    const float* x      = (const float*)d_in[0];
    const float* weight = (const float*)d_in[1];
    const float* bias   = (const float*)d_in[2];
    const float* ka_w1 = (const float*)d_in[3],  *ka_b1 = (const float*)d_in[4];
    const float* ka_w2 = (const float*)d_in[5],  *ka_b2 = (const float*)d_in[6];
    const float* sa_w1 = (const float*)d_in[7],  *sa_b1 = (const float*)d_in[8];
    const float* sa_w2 = (const float*)d_in[9],  *sa_b2 = (const float*)d_in[10];
    const float* ia_w1 = (const float*)d_in[11], *ia_b1 = (const float*)d_in[12];
    const float* ia_w2 = (const float*)d_in[13], *ia_b2 = (const float*)d_in[14];
    const float* oa_w1 = (const float*)d_in[15], *oa_b1 = (const float*)d_in[16];
    const float* oa_w2 = (const float*)d_in[17], *oa_b2 = (const float*)d_in[18];
    float* out = (float*)d_out;

    cudaFuncSetAttribute(k_gemm, cudaFuncAttributeMaxDynamicSharedMemorySize, GEMM_SMEM);

    k_prepW<<<KW * 4 * 8, 128>>>(weight);            // also zeroes g_avg
    k_prepB<<<BB * 8 * 33, 256>>>(x);                // also accumulates g_avg
    k_att<<<BB, 512>>>(ka_w1, ka_b1, ka_w2, ka_b2,
                       sa_w1, sa_b1, sa_w2, sa_b2,
                       ia_w1, ia_b1, ia_w2, ia_b2,
                       oa_w1, oa_b1, oa_w2, oa_b2);
    k_gemm<<<BB * 32 * 4, 256, GEMM_SMEM>>>(bias, out);
}

// round 9
// speedup vs baseline: 1.4435x; 1.2403x over previous
#include <cuda_runtime.h>
#include <cuda_fp16.h>
#include <cstdint>
#include <cstddef>

#define DI __device__ __forceinline__

// ---------------- problem constants ----------------
constexpr int BB = 8, CI = 512, CO = 512, KW = 5, LL = 4096;

// ---------------- GEMM tiling ----------------
constexpr int NIT = 40;                      // kw(5) outer x ic(8) inner
constexpr int TILE_B = 16384;                // 128 rows x 128B
constexpr int STAGE_B = 2 * TILE_B;          // 32 KB (A + B)
constexpr int NSTAGE = 3;
constexpr int GEMM_SMEM = NSTAGE * STAGE_B;  // 96 KB

constexpr int BROWS = 4224;                  // g_Bx rows (33*128)

// ---------------- device scratch ----------------
// x rows: [b][ic(8)][gl(4224)] x 64 halfs (128B rows), swizzle phase = gl&7; l = gl-2
__device__ __half g_Bx[(size_t)BB * 8 * BROWS * 64];
// weight tiles (batch-independent): [k][oT(4)][ic(8)], 128x128B swizzled tiles
__device__ __half g_W[(size_t)KW * 4 * 8 * 8192];
__device__ float  g_avg[BB * CI];
__device__ float  g_h[BB * 4 * 128];
__device__ float  g_ka[BB * KW];
__device__ float  g_scale[BB * CO];

// ---------------- helpers ----------------
DI uint32_t smem_u32(const void* p) {
    uint32_t a;
    asm("{ .reg .u64 t; cvta.to.shared.u64 t, %1; cvt.u32.u64 %0, t; }" : "=r"(a) : "l"(p));
    return a;
}
DI uint32_t swz(uint32_t off) { return off ^ ((off >> 3) & 0x70); }
DI void cp16(uint32_t dst, const void* src) {
    asm volatile("cp.async.cg.shared.global [%0], [%1], 16;" :: "r"(dst), "l"(src) : "memory");
}
DI void cp_commit() { asm volatile("cp.async.commit_group;" ::: "memory"); }
template <int N> DI void cp_wait() { asm volatile("cp.async.wait_group %0;" :: "n"(N) : "memory"); }

DI void ldmx4(uint32_t& r0, uint32_t& r1, uint32_t& r2, uint32_t& r3, uint32_t a) {
    asm volatile("ldmatrix.sync.aligned.m8n8.x4.shared.b16 {%0,%1,%2,%3}, [%4];"
                 : "=r"(r0), "=r"(r1), "=r"(r2), "=r"(r3) : "r"(a));
}
DI void mma16816(float* c, const uint32_t* a, const uint32_t* b) {
    asm volatile(
        "mma.sync.aligned.m16n8k16.row.col.f32.f16.f16.f32 "
        "{%0,%1,%2,%3}, {%4,%5,%6,%7}, {%8,%9}, {%0,%1,%2,%3};"
        : "+f"(c[0]), "+f"(c[1]), "+f"(c[2]), "+f"(c[3])
        : "r"(a[0]), "r"(a[1]), "r"(a[2]), "r"(a[3]), "r"(b[0]), "r"(b[1]));
}

// ---------------- kernel 1: weight -> fp16 swizzled tiles + zero g_avg --------------
__global__ void k_prepW(const float* __restrict__ w) {
    int bx = blockIdx.x;
    int oT = bx >> 3, ic = bx & 7;
    int tid = threadIdx.x;
    if (bx < 16) g_avg[bx * 256 + tid] = 0.f;     // zero before prepB atomics
#pragma unroll 1
    for (int p = tid; p < 4096; p += 256) {       // 128 o-rows x 32 j2
        int ol = p >> 5, j2 = p & 31;
        int o = oT * 128 + ol;
        int i = ic * 64 + 2 * j2;
        const float* src = w + ((size_t)o * CI + i) * KW;   // 10 consecutive floats
        float v[10];
#pragma unroll
        for (int q = 0; q < 10; ++q) v[q] = src[q];
        uint32_t off = swz((uint32_t)ol * 128 + j2 * 4);
#pragma unroll
        for (int k = 0; k < KW; ++k) {
            __half2 hv = __floats2half2_rn(v[k], v[5 + k]);
            char* tile = (char*)g_W + (size_t)((k * 4 + oT) * 8 + ic) * TILE_B;
            *(uint32_t*)(tile + off) = *(uint32_t*)&hv;
        }
    }
}

// ---------------- kernel 2: x -> fp16 transposed swizzled rows + fused mean --------
__global__ void k_prepB(const float* __restrict__ x) {
    __shared__ float xs[128][65];        // [l offset][channel]
    int bx = blockIdx.x;                 // b*(8*33) + ic*33 + g
    int g = bx % 33;
    int ic = (bx / 33) & 7;
    int b = bx / (33 * 8);
    int tid = threadIdx.x;               // 256 threads
    for (int e = tid; e < 64 * 128; e += 256) {
        int c = e >> 7, off = e & 127;
        int l = g * 128 - 2 + off;
        float v = 0.f;
        if (l >= 0 && l < LL)
            v = x[((size_t)(b * CI + ic * 64 + c)) * LL + l];
        xs[off][c] = v;
    }
    __syncthreads();

    // fused avg: each l appears in exactly one (g,off) pair across blocks
    {
        int c = tid >> 2, part = tid & 3;
        float s = 0.f;
#pragma unroll
        for (int q = 0; q < 32; ++q) s += xs[part * 32 + q][c];
        s += __shfl_xor_sync(0xFFFFFFFFu, s, 1);
        s += __shfl_xor_sync(0xFFFFFFFFu, s, 2);
        if (part == 0)
            atomicAdd(&g_avg[b * CI + ic * 64 + c], s * (1.f / (float)LL));
    }

    char* base = (char*)g_Bx + ((size_t)(b * 8 + ic) * BROWS + (size_t)g * 128) * 128;
#pragma unroll
    for (int q = 0; q < 4; ++q) {
        int idx = tid + q * 256;
        int r = idx >> 3, j = idx & 7;
        uint32_t u[4];
#pragma unroll
        for (int p = 0; p < 4; ++p) {
            __half2 hv = __floats2half2_rn(xs[r][j * 8 + 2 * p], xs[r][j * 8 + 2 * p + 1]);
            u[p] = *(uint32_t*)&hv;
        }
        uint32_t off = (uint32_t)(j * 16) ^ (uint32_t)((r & 7) * 16);
        *(uint4*)(base + (size_t)r * 128 + off) = make_uint4(u[0], u[1], u[2], u[3]);
    }
}

// ---------------- kernel 3a: attention layer 1 (32 blocks) ----------------
__global__ void k_att1(
    const float* ka_w1, const float* ka_b1,
    const float* sa_w1, const float* sa_b1,
    const float* ia_w1, const float* ia_b1,
    const float* oa_w1, const float* oa_b1) {
    __shared__ float avgs[CI];
    int br = blockIdx.x & 3, b = blockIdx.x >> 2;
    int row = threadIdx.x;               // 128 threads
#pragma unroll
    for (int q = 0; q < 4; ++q) avgs[row + q * 128] = g_avg[b * CI + row + q * 128];
    __syncthreads();
    const float* w1 = br == 0 ? ka_w1 : br == 1 ? sa_w1 : br == 2 ? ia_w1 : oa_w1;
    const float* b1 = br == 0 ? ka_b1 : br == 1 ? sa_b1 : br == 2 ? ia_b1 : oa_b1;
    float s = b1[row];
    const float* wr = w1 + (size_t)row * CI;
#pragma unroll 8
    for (int u = 0; u < CI; ++u) s += avgs[u] * wr[u];
    g_h[(b * 4 + br) * 128 + row] = fmaxf(s, 0.f);
}

// ---------------- kernel 3b: attention layer 2 (8 blocks) ----------------
__global__ void k_att2(
    const float* ka_w2, const float* ka_b2,
    const float* sa_w2, const float* sa_b2,
    const float* ia_w2, const float* ia_b2,
    const float* oa_w2, const float* oa_b2) {
    __shared__ float h[4][128];
    __shared__ float sav;
    int b = blockIdx.x, t = threadIdx.x;   // 512 threads
    h[t >> 7][t & 127] = g_h[b * 512 + t];
    __syncthreads();

    float s2 = oa_b2[t];
    const float* w2r = oa_w2 + (size_t)t * 128;
#pragma unroll 8
    for (int r = 0; r < 128; ++r) s2 += h[3][r] * w2r[r];
    float oav = 1.f / (1.f + expf(-s2));

    float s3 = ia_b2[t];
    const float* w3r = ia_w2 + (size_t)t * 128;
#pragma unroll 8
    for (int r = 0; r < 128; ++r) s3 += h[2][r] * w3r[r];
    float iav = 1.f / (1.f + expf(-s3));

    if (t < KW) {
        float s4 = ka_b2[t];
        const float* w4r = ka_w2 + (size_t)t * 128;
#pragma unroll 8
        for (int r = 0; r < 128; ++r) s4 += h[0][r] * w4r[r];
        g_ka[b * KW + t] = 1.f / (1.f + expf(-s4));
    }
    if (t == 256) {
        float s5 = sa_b2[0];
#pragma unroll 8
        for (int r = 0; r < 128; ++r) s5 += h[1][r] * sa_w2[r];
        sav = 1.f / (1.f + expf(-s5));
    }
    __syncthreads();
    g_scale[b * CO + t] = sav * iav * oav;
}

// ---------------- kernel 4: HMMA GEMM (BM128 x BN128) ----------------
__global__ void __launch_bounds__(256, 2)
k_gemm(const float* __restrict__ bias, float* __restrict__ out) {
    extern __shared__ char sm[];
    uint32_t sbase = smem_u32(sm);
    int tid = threadIdx.x, lane = tid & 31, wid = tid >> 5;
    int bx = blockIdx.x;
    int oT = bx & 3, lT = (bx >> 2) & 31, b = bx >> 7;
    int wm = (wid & 1) * 64, wn = (wid >> 1) * 32;

    const char* wb = (const char*)g_W;
    const char* bb = (const char*)g_Bx;

    __half2 kh[KW];
#pragma unroll
    for (int k = 0; k < KW; ++k) {
        float kv = g_ka[b * KW + k];
        kh[k] = __floats2half2_rn(kv, kv);
    }

    // iteration j: kw = j>>3 (outer), ic = j&7 (inner)
    auto issue = [&](int j, int s) {
        int kw = j >> 3, ic = j & 7;
        const char* sA = wb + (size_t)((kw * 4 + oT) * 8 + ic) * TILE_B;
        const char* sB = bb + ((size_t)(b * 8 + ic) * BROWS + (size_t)(lT * 128 + kw)) * 128;
        uint32_t dA = sbase + s * STAGE_B;
        uint32_t dB = dA + TILE_B;
#pragma unroll
        for (int q = 0; q < 4; ++q) {
            int c = (tid + q * 256) * 16;
            cp16(dA + c, sA + c);
        }
#pragma unroll
        for (int q = 0; q < 4; ++q) {
            int c = (tid + q * 256) * 16;
            cp16(dB + c, sB + c);
        }
    };

    float acc[4][4][4];
#pragma unroll
    for (int mi = 0; mi < 4; ++mi)
#pragma unroll
        for (int ni = 0; ni < 4; ++ni)
#pragma unroll
            for (int r = 0; r < 4; ++r) acc[mi][ni][r] = 0.f;

    int rowA = (lane & 7) + 8 * ((lane >> 3) & 1);
    int colA = (lane >> 4) * 16;
    uint32_t axor = (uint32_t)((lane & 7) << 4);
    // B ldmx4 lane mapping: lanes 0-7 m0(n0-7,k0-15lo), 8-15 m1(n0-7,k hi),
    //                       16-23 m2(n8-15,k lo), 24-31 m3(n8-15,k hi)
    int nOffB = ((lane >> 4) & 1) * 8 + (lane & 7);
    int colB = ((lane >> 3) & 1) * 16;

    issue(0, 0); cp_commit();
    issue(1, 1); cp_commit();

#pragma unroll 1
    for (int it = 0; it < NIT; ++it) {
        cp_wait<1>();
        __syncthreads();                        // all warps done reading stage (it-1)%3

        int j2 = it + 2;
        if (j2 < NIT) issue(j2, j2 % 3);        // overwrites stage (it-1)%3
        cp_commit();

        int kw = it >> 3;
        // kw shift applied at cp.async; only the swizzle PHASE depends on kw here
        uint32_t bxor = (uint32_t)(((kw + (lane & 7)) & 7) << 4);
        __half2 kk = kh[kw];
        uint32_t sA = sbase + (it % 3) * STAGE_B;
        uint32_t sB = sA + TILE_B;
        uint32_t bRow0 = (uint32_t)(wn + nOffB);      // NO kw here (bugfix)
        uint32_t bRow1 = bRow0 + 16;
#pragma unroll
        for (int ks = 0; ks < 4; ++ks) {
            uint32_t afr[4][4], bfr[2][4];
#pragma unroll
            for (int mi = 0; mi < 4; ++mi)
                ldmx4(afr[mi][0], afr[mi][1], afr[mi][2], afr[mi][3],
                      (sA + (uint32_t)(wm + mi * 16 + rowA) * 128 + ks * 32 + colA) ^ axor);
#pragma unroll
            for (int nb = 0; nb < 2; ++nb) {
                uint32_t br = nb ? bRow1 : bRow0;
                ldmx4(bfr[nb][0], bfr[nb][1], bfr[nb][2], bfr[nb][3],
                      (sB + br * 128 + ks * 32 + colB) ^ bxor);
#pragma unroll
                for (int q = 0; q < 4; ++q)
                    *(__half2*)&bfr[nb][q] = __hmul2(*(__half2*)&bfr[nb][q], kk);
            }
#pragma unroll
            for (int mi = 0; mi < 4; ++mi)
#pragma unroll
                for (int nb = 0; nb < 2; ++nb) {
                    mma16816(acc[mi][nb * 2],     afr[mi], &bfr[nb][0]);
                    mma16816(acc[mi][nb * 2 + 1], afr[mi], &bfr[nb][2]);
                }
        }
    }

    // epilogue: scale*acc + bias; ni -> n col = wn + (ni>>1)*16 + (ni&1)*8
    int r0 = wm + (lane >> 2);
    float scb[4][2], bib[4][2];
#pragma unroll
    for (int mi = 0; mi < 4; ++mi) {
        int o0 = oT * 128 + r0 + mi * 16;
        scb[mi][0] = g_scale[b * CO + o0];
        scb[mi][1] = g_scale[b * CO + o0 + 8];
        bib[mi][0] = bias[o0];
        bib[mi][1] = bias[o0 + 8];
    }
    float* ob = out + ((size_t)(b * CO + oT * 128)) * LL + lT * 128;
#pragma unroll
    for (int mi = 0; mi < 4; ++mi) {
#pragma unroll
        for (int ni = 0; ni < 4; ++ni) {
            int rr = r0 + mi * 16;
            int cc = wn + (ni >> 1) * 16 + (ni & 1) * 8 + (lane & 3) * 2;
            float2 v0 = make_float2(scb[mi][0] * acc[mi][ni][0] + bib[mi][0],
                                    scb[mi][0] * acc[mi][ni][1] + bib[mi][0]);
            float2 v1 = make_float2(scb[mi][1] * acc[mi][ni][2] + bib[mi][1],
                                    scb[mi][1] * acc[mi][ni][3] + bib[mi][1]);
            *(float2*)(ob + (size_t)rr * LL + cc) = v0;
            *(float2*)(ob + (size_t)(rr + 8) * LL + cc) = v1;
        }
    }
}

// ---------------- launch ----------------
extern "C" void kernel_launch(void* const* d_in, const int* in_sizes, int n_in,
                              void* d_out, int out_size) {
    const float* x      = (const float*)d_in[0];
    const float* weight = (const float*)d_in[1];
    const float* bias   = (const float*)d_in[2];
    const float* ka_w1 = (const float*)d_in[3],  *ka_b1 = (const float*)d_in[4];
    const float* ka_w2 = (const float*)d_in[5],  *ka_b2 = (const float*)d_in[6];
    const float* sa_w1 = (const float*)d_in[7],  *sa_b1 = (const float*)d_in[8];
    const float* sa_w2 = (const float*)d_in[9],  *sa_b2 = (const float*)d_in[10];
    const float* ia_w1 = (const float*)d_in[11], *ia_b1 = (const float*)d_in[12];
    const float* ia_w2 = (const float*)d_in[13], *ia_b2 = (const float*)d_in[14];
    const float* oa_w1 = (const float*)d_in[15], *oa_b1 = (const float*)d_in[16];
    const float* oa_w2 = (const float*)d_in[17], *oa_b2 = (const float*)d_in[18];
    float* out = (float*)d_out;

    cudaFuncSetAttribute(k_gemm, cudaFuncAttributeMaxDynamicSharedMemorySize, GEMM_SMEM);

    k_prepW<<<32, 256>>>(weight);                    // also zeroes g_avg
    k_prepB<<<BB * 8 * 33, 256>>>(x);                // also accumulates g_avg
    k_att1<<<BB * 4, 128>>>(ka_w1, ka_b1, sa_w1, sa_b1, ia_w1, ia_b1, oa_w1, oa_b1);
    k_att2<<<BB, 512>>>(ka_w2, ka_b2, sa_w2, sa_b2, ia_w2, ia_b2, oa_w2, oa_b2);
    k_gemm<<<BB * 32 * 4, 256, GEMM_SMEM>>>(bias, out);
}

// round 10
// speedup vs baseline: 1.8693x; 1.2949x over previous
#include <cuda_runtime.h>
#include <cuda_fp16.h>
#include <cstdint>
#include <cstddef>

#define DI __device__ __forceinline__

// ---------------- problem constants ----------------
constexpr int BB = 8, CI = 512, CO = 512, KW = 5, LL = 4096;

// ---------------- GEMM tiling ----------------
constexpr int NIT = 40;                      // kw(5) outer x ic(8) inner
constexpr int TILE_B = 16384;                // 128 rows x 128B
constexpr int STAGE_B = 2 * TILE_B;          // 32 KB (A + B)
constexpr int NSTAGE = 3;
constexpr int GEMM_SMEM = NSTAGE * STAGE_B;  // 96 KB

constexpr int BROWS = 4224;                  // g_Bx rows (33*128)

// ---------------- device scratch ----------------
__device__ __half g_Bx[(size_t)BB * 8 * BROWS * 64];
__device__ __half g_W[(size_t)KW * 4 * 8 * 8192];
__device__ float  g_avg[BB * CI];
__device__ float  g_h[BB * 4 * 128];
__device__ float  g_ka[BB * KW];
__device__ float  g_scale[BB * CO];

// ---------------- helpers ----------------
DI uint32_t smem_u32(const void* p) {
    uint32_t a;
    asm("{ .reg .u64 t; cvta.to.shared.u64 t, %1; cvt.u32.u64 %0, t; }" : "=r"(a) : "l"(p));
    return a;
}
DI uint32_t swz(uint32_t off) { return off ^ ((off >> 3) & 0x70); }
DI void cp16(uint32_t dst, const void* src) {
    asm volatile("cp.async.cg.shared.global [%0], [%1], 16;" :: "r"(dst), "l"(src) : "memory");
}
DI void cp_commit() { asm volatile("cp.async.commit_group;" ::: "memory"); }
template <int N> DI void cp_wait() { asm volatile("cp.async.wait_group %0;" :: "n"(N) : "memory"); }

DI void ldmx4(uint32_t& r0, uint32_t& r1, uint32_t& r2, uint32_t& r3, uint32_t a) {
    asm volatile("ldmatrix.sync.aligned.m8n8.x4.shared.b16 {%0,%1,%2,%3}, [%4];"
                 : "=r"(r0), "=r"(r1), "=r"(r2), "=r"(r3) : "r"(a));
}
DI void mma16816(float* c, const uint32_t* a, const uint32_t* b) {
    asm volatile(
        "mma.sync.aligned.m16n8k16.row.col.f32.f16.f16.f32 "
        "{%0,%1,%2,%3}, {%4,%5,%6,%7}, {%8,%9}, {%0,%1,%2,%3};"
        : "+f"(c[0]), "+f"(c[1]), "+f"(c[2]), "+f"(c[3])
        : "r"(a[0]), "r"(a[1]), "r"(a[2]), "r"(a[3]), "r"(b[0]), "r"(b[1]));
}
DI float dot4(float4 a, float4 b) {
    return a.x * b.x + a.y * b.y + a.z * b.z + a.w * b.w;
}

// ---------------- kernel 1: weight -> fp16 swizzled tiles + zero g_avg --------------
__global__ void k_prepW(const float* __restrict__ w) {
    int bx = blockIdx.x;
    int oT = bx >> 3, ic = bx & 7;
    int tid = threadIdx.x;
    if (bx < 16) g_avg[bx * 256 + tid] = 0.f;
#pragma unroll 1
    for (int p = tid; p < 4096; p += 256) {       // 128 o-rows x 32 j2
        int ol = p >> 5, j2 = p & 31;
        int o = oT * 128 + ol;
        int i = ic * 64 + 2 * j2;
        const float* src = w + ((size_t)o * CI + i) * KW;
        float v[10];
#pragma unroll
        for (int q = 0; q < 10; ++q) v[q] = src[q];
        uint32_t off = swz((uint32_t)ol * 128 + j2 * 4);
#pragma unroll
        for (int k = 0; k < KW; ++k) {
            __half2 hv = __floats2half2_rn(v[k], v[5 + k]);
            char* tile = (char*)g_W + (size_t)((k * 4 + oT) * 8 + ic) * TILE_B;
            *(uint32_t*)(tile + off) = *(uint32_t*)&hv;
        }
    }
}

// ---------------- kernel 2: x -> fp16 transposed swizzled rows + fused mean --------
__global__ void k_prepB(const float* __restrict__ x) {
    __shared__ float xs[128][65];
    int bx = blockIdx.x;                 // b*(8*33) + ic*33 + g
    int g = bx % 33;
    int ic = (bx / 33) & 7;
    int b = bx / (33 * 8);
    int tid = threadIdx.x;               // 256 threads
    for (int e = tid; e < 64 * 128; e += 256) {
        int c = e >> 7, off = e & 127;
        int l = g * 128 - 2 + off;
        float v = 0.f;
        if (l >= 0 && l < LL)
            v = x[((size_t)(b * CI + ic * 64 + c)) * LL + l];
        xs[off][c] = v;
    }
    __syncthreads();

    {
        int c = tid >> 2, part = tid & 3;
        float s = 0.f;
#pragma unroll
        for (int q = 0; q < 32; ++q) s += xs[part * 32 + q][c];
        s += __shfl_xor_sync(0xFFFFFFFFu, s, 1);
        s += __shfl_xor_sync(0xFFFFFFFFu, s, 2);
        if (part == 0)
            atomicAdd(&g_avg[b * CI + ic * 64 + c], s * (1.f / (float)LL));
    }

    char* base = (char*)g_Bx + ((size_t)(b * 8 + ic) * BROWS + (size_t)g * 128) * 128;
#pragma unroll
    for (int q = 0; q < 4; ++q) {
        int idx = tid + q * 256;
        int r = idx >> 3, j = idx & 7;
        uint32_t u[4];
#pragma unroll
        for (int p = 0; p < 4; ++p) {
            __half2 hv = __floats2half2_rn(xs[r][j * 8 + 2 * p], xs[r][j * 8 + 2 * p + 1]);
            u[p] = *(uint32_t*)&hv;
        }
        uint32_t off = (uint32_t)(j * 16) ^ (uint32_t)((r & 7) * 16);
        *(uint4*)(base + (size_t)r * 128 + off) = make_uint4(u[0], u[1], u[2], u[3]);
    }
}

// ---------------- kernel 3a: attention layer 1 (32 blocks, 256 thr, float4) --------
__global__ void k_att1(
    const float* ka_w1, const float* ka_b1,
    const float* sa_w1, const float* sa_b1,
    const float* ia_w1, const float* ia_b1,
    const float* oa_w1, const float* oa_b1) {
    __shared__ float avgs[CI];
    int br = blockIdx.x & 3, b = blockIdx.x >> 2;
    int t = threadIdx.x;                 // 256 threads; 2 per output row
    avgs[t] = g_avg[b * CI + t];
    avgs[t + 256] = g_avg[b * CI + t + 256];
    __syncthreads();
    const float* w1 = br == 0 ? ka_w1 : br == 1 ? sa_w1 : br == 2 ? ia_w1 : oa_w1;
    const float* b1 = br == 0 ? ka_b1 : br == 1 ? sa_b1 : br == 2 ? ia_b1 : oa_b1;
    int row = t >> 1, half = t & 1;
    const float4* wr = (const float4*)(w1 + (size_t)row * CI) + half * 64;
    const float4* av = (const float4*)avgs + half * 64;
    float s = 0.f;
#pragma unroll 8
    for (int q = 0; q < 64; ++q) s += dot4(wr[q], av[q]);
    s += __shfl_xor_sync(0xFFFFFFFFu, s, 1);
    if (half == 0)
        g_h[(b * 4 + br) * 128 + row] = fmaxf(s + b1[row], 0.f);
}

// ---------------- kernel 3b: attention layer 2 (32 blocks, 256 thr, float4) --------
__global__ void k_att2(
    const float* ka_w2, const float* ka_b2,
    const float* sa_w2, const float* sa_b2,
    const float* ia_w2, const float* ia_b2,
    const float* oa_w2, const float* oa_b2) {
    __shared__ float h[4 * 128];
    __shared__ float sav;
    int bx = blockIdx.x;
    int seg = bx & 3, b = bx >> 2;
    int t = threadIdx.x;                 // 256 threads
    h[t] = g_h[b * 512 + t];
    h[t + 256] = g_h[b * 512 + t + 256];
    __syncthreads();

    int o = seg * 128 + (t >> 1), half = t & 1;
    const float4* hoa = (const float4*)(h + 3 * 128) + half * 16;
    const float4* woa = (const float4*)(oa_w2 + (size_t)o * 128) + half * 16;
    const float4* hia = (const float4*)(h + 2 * 128) + half * 16;
    const float4* wia = (const float4*)(ia_w2 + (size_t)o * 128) + half * 16;
    float so = 0.f, si = 0.f;
#pragma unroll 8
    for (int q = 0; q < 16; ++q) {
        so += dot4(woa[q], hoa[q]);
        si += dot4(wia[q], hia[q]);
    }
    so += __shfl_xor_sync(0xFFFFFFFFu, so, 1);
    si += __shfl_xor_sync(0xFFFFFFFFu, si, 1);

    // sav: warp 0, one float4 per lane + warp reduce (redundant per block)
    if (t < 32) {
        float ss = dot4(((const float4*)sa_w2)[t], ((const float4*)(h + 128))[t]);
#pragma unroll
        for (int off = 16; off; off >>= 1) ss += __shfl_xor_sync(0xFFFFFFFFu, ss, off);
        if (t == 0) sav = 1.f / (1.f + expf(-(ss + sa_b2[0])));
    }
    // ka: seg-0 blocks only, 5 threads
    if (seg == 0 && t >= 64 && t < 64 + KW) {
        int kk = t - 64;
        const float4* wka = (const float4*)(ka_w2 + (size_t)kk * 128);
        const float4* hka = (const float4*)h;
        float sk = 0.f;
#pragma unroll 8
        for (int q = 0; q < 32; ++q) sk += dot4(wka[q], hka[q]);
        g_ka[b * KW + kk] = 1.f / (1.f + expf(-(sk + ka_b2[kk])));
    }
    __syncthreads();
    if (half == 0) {
        float oav = 1.f / (1.f + expf(-(so + oa_b2[o])));
        float iav = 1.f / (1.f + expf(-(si + ia_b2[o])));
        g_scale[b * CO + o] = sav * iav * oav;
    }
}

// ---------------- kernel 4: HMMA GEMM (BM128 x BN128) ----------------
__global__ void __launch_bounds__(256, 2)
k_gemm(const float* __restrict__ bias, float* __restrict__ out) {
    extern __shared__ char sm[];
    uint32_t sbase = smem_u32(sm);
    int tid = threadIdx.x, lane = tid & 31, wid = tid >> 5;
    int bx = blockIdx.x;
    int oT = bx & 3, lT = (bx >> 2) & 31, b = bx >> 7;
    int wm = (wid & 1) * 64, wn = (wid >> 1) * 32;

    const char* wb = (const char*)g_W;
    const char* bb = (const char*)g_Bx;

    __half2 kh[KW];
#pragma unroll
    for (int k = 0; k < KW; ++k) {
        float kv = g_ka[b * KW + k];
        kh[k] = __floats2half2_rn(kv, kv);
    }

    auto issue = [&](int j, int s) {
        int kw = j >> 3, ic = j & 7;
        const char* sA = wb + (size_t)((kw * 4 + oT) * 8 + ic) * TILE_B;
        const char* sB = bb + ((size_t)(b * 8 + ic) * BROWS + (size_t)(lT * 128 + kw)) * 128;
        uint32_t dA = sbase + s * STAGE_B;
        uint32_t dB = dA + TILE_B;
#pragma unroll
        for (int q = 0; q < 4; ++q) {
            int c = (tid + q * 256) * 16;
            cp16(dA + c, sA + c);
        }
#pragma unroll
        for (int q = 0; q < 4; ++q) {
            int c = (tid + q * 256) * 16;
            cp16(dB + c, sB + c);
        }
    };

    float acc[4][4][4];
#pragma unroll
    for (int mi = 0; mi < 4; ++mi)
#pragma unroll
        for (int ni = 0; ni < 4; ++ni)
#pragma unroll
            for (int r = 0; r < 4; ++r) acc[mi][ni][r] = 0.f;

    int rowA = (lane & 7) + 8 * ((lane >> 3) & 1);
    int colA = (lane >> 4) * 16;
    uint32_t axor = (uint32_t)((lane & 7) << 4);
    int nOffB = ((lane >> 4) & 1) * 8 + (lane & 7);
    int colB = ((lane >> 3) & 1) * 16;

    issue(0, 0); cp_commit();
    issue(1, 1); cp_commit();

#pragma unroll 1
    for (int it = 0; it < NIT; ++it) {
        cp_wait<1>();
        __syncthreads();

        int j2 = it + 2;
        if (j2 < NIT) issue(j2, j2 % 3);
        cp_commit();

        int kw = it >> 3;
        uint32_t bxor = (uint32_t)(((kw + (lane & 7)) & 7) << 4);
        __half2 kk = kh[kw];
        uint32_t sA = sbase + (it % 3) * STAGE_B;
        uint32_t sB = sA + TILE_B;
        uint32_t bRow0 = (uint32_t)(wn + nOffB);
        uint32_t bRow1 = bRow0 + 16;
#pragma unroll
        for (int ks = 0; ks < 4; ++ks) {
            uint32_t afr[4][4], bfr[2][4];
#pragma unroll
            for (int mi = 0; mi < 4; ++mi)
                ldmx4(afr[mi][0], afr[mi][1], afr[mi][2], afr[mi][3],
                      (sA + (uint32_t)(wm + mi * 16 + rowA) * 128 + ks * 32 + colA) ^ axor);
#pragma unroll
            for (int nb = 0; nb < 2; ++nb) {
                uint32_t br = nb ? bRow1 : bRow0;
                ldmx4(bfr[nb][0], bfr[nb][1], bfr[nb][2], bfr[nb][3],
                      (sB + br * 128 + ks * 32 + colB) ^ bxor);
#pragma unroll
                for (int q = 0; q < 4; ++q)
                    *(__half2*)&bfr[nb][q] = __hmul2(*(__half2*)&bfr[nb][q], kk);
            }
#pragma unroll
            for (int mi = 0; mi < 4; ++mi)
#pragma unroll
                for (int nb = 0; nb < 2; ++nb) {
                    mma16816(acc[mi][nb * 2],     afr[mi], &bfr[nb][0]);
                    mma16816(acc[mi][nb * 2 + 1], afr[mi], &bfr[nb][2]);
                }
        }
    }

    int r0 = wm + (lane >> 2);
    float scb[4][2], bib[4][2];
#pragma unroll
    for (int mi = 0; mi < 4; ++mi) {
        int o0 = oT * 128 + r0 + mi * 16;
        scb[mi][0] = g_scale[b * CO + o0];
        scb[mi][1] = g_scale[b * CO + o0 + 8];
        bib[mi][0] = bias[o0];
        bib[mi][1] = bias[o0 + 8];
    }
    float* ob = out + ((size_t)(b * CO + oT * 128)) * LL + lT * 128;
#pragma unroll
    for (int mi = 0; mi < 4; ++mi) {
#pragma unroll
        for (int ni = 0; ni < 4; ++ni) {
            int rr = r0 + mi * 16;
            int cc = wn + (ni >> 1) * 16 + (ni & 1) * 8 + (lane & 3) * 2;
            float2 v0 = make_float2(scb[mi][0] * acc[mi][ni][0] + bib[mi][0],
                                    scb[mi][0] * acc[mi][ni][1] + bib[mi][0]);
            float2 v1 = make_float2(scb[mi][1] * acc[mi][ni][2] + bib[mi][1],
                                    scb[mi][1] * acc[mi][ni][3] + bib[mi][1]);
            *(float2*)(ob + (size_t)rr * LL + cc) = v0;
            *(float2*)(ob + (size_t)(rr + 8) * LL + cc) = v1;
        }
    }
}

// ---------------- launch ----------------
extern "C" void kernel_launch(void* const* d_in, const int* in_sizes, int n_in,
                              void* d_out, int out_size) {
    const float* x      = (const float*)d_in[0];
    const float* weight = (const float*)d_in[1];
    const float* bias   = (const float*)d_in[2];
    const float* ka_w1 = (const float*)d_in[3],  *ka_b1 = (const float*)d_in[4];
    const float* ka_w2 = (const float*)d_in[5],  *ka_b2 = (const float*)d_in[6];
    const float* sa_w1 = (const float*)d_in[7],  *sa_b1 = (const float*)d_in[8];
    const float* sa_w2 = (const float*)d_in[9],  *sa_b2 = (const float*)d_in[10];
    const float* ia_w1 = (const float*)d_in[11], *ia_b1 = (const float*)d_in[12];
    const float* ia_w2 = (const float*)d_in[13], *ia_b2 = (const float*)d_in[14];
    const float* oa_w1 = (const float*)d_in[15], *oa_b1 = (const float*)d_in[16];
    const float* oa_w2 = (const float*)d_in[17], *oa_b2 = (const float*)d_in[18];
    float* out = (float*)d_out;

    cudaFuncSetAttribute(k_gemm, cudaFuncAttributeMaxDynamicSharedMemorySize, GEMM_SMEM);

    k_prepW<<<32, 256>>>(weight);
    k_prepB<<<BB * 8 * 33, 256>>>(x);
    k_att1<<<BB * 4, 256>>>(ka_w1, ka_b1, sa_w1, sa_b1, ia_w1, ia_b1, oa_w1, oa_b1);
    k_att2<<<BB * 4, 256>>>(ka_w2, ka_b2, sa_w2, sa_b2, ia_w2, ia_b2, oa_w2, oa_b2);
    k_gemm<<<BB * 32 * 4, 256, GEMM_SMEM>>>(bias, out);
}

// round 11
// speedup vs baseline: 2.0275x; 1.0847x over previous
#include <cuda_runtime.h>
#include <cuda_fp16.h>
#include <cstdint>
#include <cstddef>

#define DI __device__ __forceinline__

// ---------------- problem constants ----------------
constexpr int BB = 8, CI = 512, CO = 512, KW = 5, LL = 4096;

// ---------------- GEMM tiling ----------------
constexpr int NIT = 40;                      // kw(5) outer x ic(8) inner
constexpr int TILE_B = 16384;                // 128 rows x 128B
constexpr int STAGE_B = 2 * TILE_B;          // 32 KB (A + B)
constexpr int NSTAGE = 3;
constexpr int GEMM_SMEM = NSTAGE * STAGE_B;  // 96 KB

constexpr int BROWS = 4224;                  // g_Bx rows (33*128)

// ---------------- device scratch ----------------
__device__ __half g_Bx[(size_t)BB * 8 * BROWS * 64];
__device__ __half g_W[(size_t)KW * 4 * 8 * 8192];
__device__ float  g_avg[BB * CI];
__device__ float  g_h[BB * 4 * 128];
__device__ float  g_ka[BB * KW];
__device__ float  g_scale[BB * CO];

// ---------------- helpers ----------------
DI uint32_t smem_u32(const void* p) {
    uint32_t a;
    asm("{ .reg .u64 t; cvta.to.shared.u64 t, %1; cvt.u32.u64 %0, t; }" : "=r"(a) : "l"(p));
    return a;
}
DI uint32_t swz(uint32_t off) { return off ^ ((off >> 3) & 0x70); }
DI void cp16(uint32_t dst, const void* src) {
    asm volatile("cp.async.cg.shared.global [%0], [%1], 16;" :: "r"(dst), "l"(src) : "memory");
}
DI void cp_commit() { asm volatile("cp.async.commit_group;" ::: "memory"); }
template <int N> DI void cp_wait() { asm volatile("cp.async.wait_group %0;" :: "n"(N) : "memory"); }

DI void ldmx4(uint32_t& r0, uint32_t& r1, uint32_t& r2, uint32_t& r3, uint32_t a) {
    asm volatile("ldmatrix.sync.aligned.m8n8.x4.shared.b16 {%0,%1,%2,%3}, [%4];"
                 : "=r"(r0), "=r"(r1), "=r"(r2), "=r"(r3) : "r"(a));
}
DI void mma16816(float* c, const uint32_t* a, const uint32_t* b) {
    asm volatile(
        "mma.sync.aligned.m16n8k16.row.col.f32.f16.f16.f32 "
        "{%0,%1,%2,%3}, {%4,%5,%6,%7}, {%8,%9}, {%0,%1,%2,%3};"
        : "+f"(c[0]), "+f"(c[1]), "+f"(c[2]), "+f"(c[3])
        : "r"(a[0]), "r"(a[1]), "r"(a[2]), "r"(a[3]), "r"(b[0]), "r"(b[1]));
}
DI float dot4(float4 a, float4 b) {
    return a.x * b.x + a.y * b.y + a.z * b.z + a.w * b.w;
}

// ---------------- kernel 1: weight -> fp16 swizzled tiles + zero g_avg --------------
__global__ void k_prepW(const float* __restrict__ w) {
    int bx = blockIdx.x;
    int oT = bx >> 3, ic = bx & 7;
    int tid = threadIdx.x;
    if (bx < 16) g_avg[bx * 256 + tid] = 0.f;
#pragma unroll 1
    for (int p = tid; p < 4096; p += 256) {       // 128 o-rows x 32 j2
        int ol = p >> 5, j2 = p & 31;
        int o = oT * 128 + ol;
        int i = ic * 64 + 2 * j2;
        const float* src = w + ((size_t)o * CI + i) * KW;
        float v[10];
#pragma unroll
        for (int q = 0; q < 10; ++q) v[q] = src[q];
        uint32_t off = swz((uint32_t)ol * 128 + j2 * 4);
#pragma unroll
        for (int k = 0; k < KW; ++k) {
            __half2 hv = __floats2half2_rn(v[k], v[5 + k]);
            char* tile = (char*)g_W + (size_t)((k * 4 + oT) * 8 + ic) * TILE_B;
            *(uint32_t*)(tile + off) = *(uint32_t*)&hv;
        }
    }
}

// ---------------- kernel 2: x -> fp16 transposed swizzled rows + fused mean --------
__global__ void k_prepB(const float* __restrict__ x) {
    __shared__ float xs[128][65];
    int bx = blockIdx.x;                 // b*(8*33) + ic*33 + g
    int g = bx % 33;
    int ic = (bx / 33) & 7;
    int b = bx / (33 * 8);
    int tid = threadIdx.x;               // 256 threads
    for (int e = tid; e < 64 * 128; e += 256) {
        int c = e >> 7, off = e & 127;
        int l = g * 128 - 2 + off;
        float v = 0.f;
        if (l >= 0 && l < LL)
            v = x[((size_t)(b * CI + ic * 64 + c)) * LL + l];
        xs[off][c] = v;
    }
    __syncthreads();

    {
        int c = tid >> 2, part = tid & 3;
        float s = 0.f;
#pragma unroll
        for (int q = 0; q < 32; ++q) s += xs[part * 32 + q][c];
        s += __shfl_xor_sync(0xFFFFFFFFu, s, 1);
        s += __shfl_xor_sync(0xFFFFFFFFu, s, 2);
        if (part == 0)
            atomicAdd(&g_avg[b * CI + ic * 64 + c], s * (1.f / (float)LL));
    }

    char* base = (char*)g_Bx + ((size_t)(b * 8 + ic) * BROWS + (size_t)g * 128) * 128;
#pragma unroll
    for (int q = 0; q < 4; ++q) {
        int idx = tid + q * 256;
        int r = idx >> 3, j = idx & 7;
        uint32_t u[4];
#pragma unroll
        for (int p = 0; p < 4; ++p) {
            __half2 hv = __floats2half2_rn(xs[r][j * 8 + 2 * p], xs[r][j * 8 + 2 * p + 1]);
            u[p] = *(uint32_t*)&hv;
        }
        uint32_t off = (uint32_t)(j * 16) ^ (uint32_t)((r & 7) * 16);
        *(uint4*)(base + (size_t)r * 128 + off) = make_uint4(u[0], u[1], u[2], u[3]);
    }
}

// ---------------- kernel 3a: attention layer 1 ----------------
__global__ void k_att1(
    const float* ka_w1, const float* ka_b1,
    const float* sa_w1, const float* sa_b1,
    const float* ia_w1, const float* ia_b1,
    const float* oa_w1, const float* oa_b1) {
    __shared__ float avgs[CI];
    int br = blockIdx.x & 3, b = blockIdx.x >> 2;
    int t = threadIdx.x;                 // 256 threads; 2 per output row
    avgs[t] = g_avg[b * CI + t];
    avgs[t + 256] = g_avg[b * CI + t + 256];
    __syncthreads();
    const float* w1 = br == 0 ? ka_w1 : br == 1 ? sa_w1 : br == 2 ? ia_w1 : oa_w1;
    const float* b1 = br == 0 ? ka_b1 : br == 1 ? sa_b1 : br == 2 ? ia_b1 : oa_b1;
    int row = t >> 1, half = t & 1;
    const float4* wr = (const float4*)(w1 + (size_t)row * CI) + half * 64;
    const float4* av = (const float4*)avgs + half * 64;
    float s = 0.f;
#pragma unroll 8
    for (int q = 0; q < 64; ++q) s += dot4(wr[q], av[q]);
    s += __shfl_xor_sync(0xFFFFFFFFu, s, 1);
    if (half == 0)
        g_h[(b * 4 + br) * 128 + row] = fmaxf(s + b1[row], 0.f);
}

// ---------------- kernel 3b: attention layer 2 ----------------
__global__ void k_att2(
    const float* ka_w2, const float* ka_b2,
    const float* sa_w2, const float* sa_b2,
    const float* ia_w2, const float* ia_b2,
    const float* oa_w2, const float* oa_b2) {
    __shared__ float h[4 * 128];
    __shared__ float sav;
    int bx = blockIdx.x;
    int seg = bx & 3, b = bx >> 2;
    int t = threadIdx.x;                 // 256 threads
    h[t] = g_h[b * 512 + t];
    h[t + 256] = g_h[b * 512 + t + 256];
    __syncthreads();

    int o = seg * 128 + (t >> 1), half = t & 1;
    const float4* hoa = (const float4*)(h + 3 * 128) + half * 16;
    const float4* woa = (const float4*)(oa_w2 + (size_t)o * 128) + half * 16;
    const float4* hia = (const float4*)(h + 2 * 128) + half * 16;
    const float4* wia = (const float4*)(ia_w2 + (size_t)o * 128) + half * 16;
    float so = 0.f, si = 0.f;
#pragma unroll 8
    for (int q = 0; q < 16; ++q) {
        so += dot4(woa[q], hoa[q]);
        si += dot4(wia[q], hia[q]);
    }
    so += __shfl_xor_sync(0xFFFFFFFFu, so, 1);
    si += __shfl_xor_sync(0xFFFFFFFFu, si, 1);

    if (t < 32) {
        float ss = dot4(((const float4*)sa_w2)[t], ((const float4*)(h + 128))[t]);
#pragma unroll
        for (int off = 16; off; off >>= 1) ss += __shfl_xor_sync(0xFFFFFFFFu, ss, off);
        if (t == 0) sav = 1.f / (1.f + expf(-(ss + sa_b2[0])));
    }
    if (seg == 0 && t >= 64 && t < 64 + KW) {
        int kk = t - 64;
        const float4* wka = (const float4*)(ka_w2 + (size_t)kk * 128);
        const float4* hka = (const float4*)h;
        float sk = 0.f;
#pragma unroll 8
        for (int q = 0; q < 32; ++q) sk += dot4(wka[q], hka[q]);
        g_ka[b * KW + kk] = 1.f / (1.f + expf(-(sk + ka_b2[kk])));
    }
    __syncthreads();
    if (half == 0) {
        float oav = 1.f / (1.f + expf(-(so + oa_b2[o])));
        float iav = 1.f / (1.f + expf(-(si + ia_b2[o])));
        g_scale[b * CO + o] = sav * iav * oav;
    }
}

// ---------------- kernel 4: HMMA GEMM, 4 warps m64n64, ka via acc rescale ----------
__global__ void __launch_bounds__(128, 2)
k_gemm(const float* __restrict__ bias, float* __restrict__ out) {
    extern __shared__ char sm[];
    uint32_t sbase = smem_u32(sm);
    int tid = threadIdx.x, lane = tid & 31, wid = tid >> 5;
    int bx = blockIdx.x;
    int oT = bx & 3, lT = (bx >> 2) & 31, b = bx >> 7;
    int wm = (wid & 1) * 64, wn = (wid >> 1) * 64;

    const char* wb = (const char*)g_W;
    const char* bb = (const char*)g_Bx;

    float kaf[KW];
#pragma unroll
    for (int k = 0; k < KW; ++k) kaf[k] = g_ka[b * KW + k];

    // iteration j: kw = j>>3 (outer), ic = j&7 (inner)
    auto issue = [&](int j, int s) {
        int kw = j >> 3, ic = j & 7;
        const char* sA = wb + (size_t)((kw * 4 + oT) * 8 + ic) * TILE_B;
        const char* sB = bb + ((size_t)(b * 8 + ic) * BROWS + (size_t)(lT * 128 + kw)) * 128;
        uint32_t dA = sbase + s * STAGE_B;
        uint32_t dB = dA + TILE_B;
#pragma unroll
        for (int q = 0; q < 8; ++q) {
            int c = (tid + q * 128) * 16;
            cp16(dA + c, sA + c);
        }
#pragma unroll
        for (int q = 0; q < 8; ++q) {
            int c = (tid + q * 128) * 16;
            cp16(dB + c, sB + c);
        }
    };

    float acc[4][8][4];
#pragma unroll
    for (int mi = 0; mi < 4; ++mi)
#pragma unroll
        for (int ni = 0; ni < 8; ++ni)
#pragma unroll
            for (int r = 0; r < 4; ++r) acc[mi][ni][r] = 0.f;

    int rowA = (lane & 7) + 8 * ((lane >> 3) & 1);
    int colA = (lane >> 4) * 16;
    uint32_t axor = (uint32_t)((lane & 7) << 4);
    int nOffB = ((lane >> 4) & 1) * 8 + (lane & 7);
    int colB = ((lane >> 3) & 1) * 16;

    issue(0, 0); cp_commit();
    issue(1, 1); cp_commit();

#pragma unroll 1
    for (int it = 0; it < NIT; ++it) {
        cp_wait<1>();
        __syncthreads();

        int j2 = it + 2;
        if (j2 < NIT) issue(j2, j2 % 3);
        cp_commit();

        int kw = it >> 3;
        // group boundary: rescale acc into units of ka[kw]
        if ((it & 7) == 0 && it > 0) {
            float r = kaf[kw - 1] / kaf[kw];
#pragma unroll
            for (int mi = 0; mi < 4; ++mi)
#pragma unroll
                for (int ni = 0; ni < 8; ++ni)
#pragma unroll
                    for (int q = 0; q < 4; ++q) acc[mi][ni][q] *= r;
        }

        uint32_t bxor = (uint32_t)(((kw + (lane & 7)) & 7) << 4);
        uint32_t sA = sbase + (it % 3) * STAGE_B;
        uint32_t sB = sA + TILE_B;
        uint32_t bRow0 = (uint32_t)(wn + nOffB);
#pragma unroll
        for (int ks = 0; ks < 4; ++ks) {
            uint32_t afr[4][4], bfr[4][4];
#pragma unroll
            for (int mi = 0; mi < 4; ++mi)
                ldmx4(afr[mi][0], afr[mi][1], afr[mi][2], afr[mi][3],
                      (sA + (uint32_t)(wm + mi * 16 + rowA) * 128 + ks * 32 + colA) ^ axor);
#pragma unroll
            for (int nb = 0; nb < 4; ++nb)
                ldmx4(bfr[nb][0], bfr[nb][1], bfr[nb][2], bfr[nb][3],
                      (sB + (bRow0 + nb * 16) * 128 + ks * 32 + colB) ^ bxor);
#pragma unroll
            for (int mi = 0; mi < 4; ++mi)
#pragma unroll
                for (int nb = 0; nb < 4; ++nb) {
                    mma16816(acc[mi][nb * 2],     afr[mi], &bfr[nb][0]);
                    mma16816(acc[mi][nb * 2 + 1], afr[mi], &bfr[nb][2]);
                }
        }
    }

    // epilogue: (scale*ka[4])*acc + bias; ni -> col = wn + (ni>>1)*16 + (ni&1)*8
    int r0 = wm + (lane >> 2);
    float ka4 = kaf[KW - 1];
    float scb[4][2], bib[4][2];
#pragma unroll
    for (int mi = 0; mi < 4; ++mi) {
        int o0 = oT * 128 + r0 + mi * 16;
        scb[mi][0] = g_scale[b * CO + o0] * ka4;
        scb[mi][1] = g_scale[b * CO + o0 + 8] * ka4;
        bib[mi][0] = bias[o0];
        bib[mi][1] = bias[o0 + 8];
    }
    float* ob = out + ((size_t)(b * CO + oT * 128)) * LL + lT * 128;
#pragma unroll
    for (int mi = 0; mi < 4; ++mi) {
#pragma unroll
        for (int ni = 0; ni < 8; ++ni) {
            int rr = r0 + mi * 16;
            int cc = wn + (ni >> 1) * 16 + (ni & 1) * 8 + (lane & 3) * 2;
            float2 v0 = make_float2(scb[mi][0] * acc[mi][ni][0] + bib[mi][0],
                                    scb[mi][0] * acc[mi][ni][1] + bib[mi][0]);
            float2 v1 = make_float2(scb[mi][1] * acc[mi][ni][2] + bib[mi][1],
                                    scb[mi][1] * acc[mi][ni][3] + bib[mi][1]);
            *(float2*)(ob + (size_t)rr * LL + cc) = v0;
            *(float2*)(ob + (size_t)(rr + 8) * LL + cc) = v1;
        }
    }
}

// ---------------- launch ----------------
extern "C" void kernel_launch(void* const* d_in, const int* in_sizes, int n_in,
                              void* d_out, int out_size) {
    const float* x      = (const float*)d_in[0];
    const float* weight = (const float*)d_in[1];
    const float* bias   = (const float*)d_in[2];
    const float* ka_w1 = (const float*)d_in[3],  *ka_b1 = (const float*)d_in[4];
    const float* ka_w2 = (const float*)d_in[5],  *ka_b2 = (const float*)d_in[6];
    const float* sa_w1 = (const float*)d_in[7],  *sa_b1 = (const float*)d_in[8];
    const float* sa_w2 = (const float*)d_in[9],  *sa_b2 = (const float*)d_in[10];
    const float* ia_w1 = (const float*)d_in[11], *ia_b1 = (const float*)d_in[12];
    const float* ia_w2 = (const float*)d_in[13], *ia_b2 = (const float*)d_in[14];
    const float* oa_w1 = (const float*)d_in[15], *oa_b1 = (const float*)d_in[16];
    const float* oa_w2 = (const float*)d_in[17], *oa_b2 = (const float*)d_in[18];
    float* out = (float*)d_out;

    cudaFuncSetAttribute(k_gemm, cudaFuncAttributeMaxDynamicSharedMemorySize, GEMM_SMEM);

    k_prepW<<<32, 256>>>(weight);
    k_prepB<<<BB * 8 * 33, 256>>>(x);
    k_att1<<<BB * 4, 256>>>(ka_w1, ka_b1, sa_w1, sa_b1, ia_w1, ia_b1, oa_w1, oa_b1);
    k_att2<<<BB * 4, 256>>>(ka_w2, ka_b2, sa_w2, sa_b2, ia_w2, ia_b2, oa_w2, oa_b2);
    k_gemm<<<BB * 32 * 4, 128, GEMM_SMEM>>>(bias, out);
}

// round 12
// speedup vs baseline: 2.0922x; 1.0319x over previous
#include <cuda_runtime.h>
#include <cuda_fp16.h>
#include <cstdint>
#include <cstddef>

#define DI __device__ __forceinline__

// ---------------- problem constants ----------------
constexpr int BB = 8, CI = 512, CO = 512, KW = 5, LL = 4096;

// ---------------- GEMM tiling ----------------
constexpr int NIT = 40;                      // kw(5) outer x ic(8) inner
constexpr int TILE_B = 16384;                // 128 rows x 128B
constexpr int STAGE_B = 2 * TILE_B;          // 32 KB (A + B)
constexpr int NSTAGE = 3;
constexpr int GEMM_SMEM = NSTAGE * STAGE_B;  // 96 KB

constexpr int BROWS = 4224;                  // g_Bx rows (33*128)

// ---------------- device scratch ----------------
__device__ __half g_Bx[(size_t)BB * 8 * BROWS * 64];
__device__ __half g_W[(size_t)KW * 4 * 8 * 8192];
__device__ float  g_avgp[BB * CI * 33];      // partial sums per (b,c,g)
__device__ float  g_h[BB * 4 * 128];
__device__ float  g_ka[BB * KW];
__device__ float  g_scale[BB * CO];

// ---------------- helpers ----------------
DI uint32_t smem_u32(const void* p) {
    uint32_t a;
    asm("{ .reg .u64 t; cvta.to.shared.u64 t, %1; cvt.u32.u64 %0, t; }" : "=r"(a) : "l"(p));
    return a;
}
DI uint32_t swz(uint32_t off) { return off ^ ((off >> 3) & 0x70); }
DI void cp16(uint32_t dst, const void* src) {
    asm volatile("cp.async.cg.shared.global [%0], [%1], 16;" :: "r"(dst), "l"(src) : "memory");
}
DI void cp_commit() { asm volatile("cp.async.commit_group;" ::: "memory"); }
template <int N> DI void cp_wait() { asm volatile("cp.async.wait_group %0;" :: "n"(N) : "memory"); }

DI void ldmx4(uint32_t& r0, uint32_t& r1, uint32_t& r2, uint32_t& r3, uint32_t a) {
    asm volatile("ldmatrix.sync.aligned.m8n8.x4.shared.b16 {%0,%1,%2,%3}, [%4];"
                 : "=r"(r0), "=r"(r1), "=r"(r2), "=r"(r3) : "r"(a));
}
DI void mma16816(float* c, const uint32_t* a, const uint32_t* b) {
    asm volatile(
        "mma.sync.aligned.m16n8k16.row.col.f32.f16.f16.f32 "
        "{%0,%1,%2,%3}, {%4,%5,%6,%7}, {%8,%9}, {%0,%1,%2,%3};"
        : "+f"(c[0]), "+f"(c[1]), "+f"(c[2]), "+f"(c[3])
        : "r"(a[0]), "r"(a[1]), "r"(a[2]), "r"(a[3]), "r"(b[0]), "r"(b[1]));
}
DI float dot4(float4 a, float4 b) {
    return a.x * b.x + a.y * b.y + a.z * b.z + a.w * b.w;
}

// ---------------- kernel 1: fused prepW (blocks 0-31) + prepB (blocks 32+) --------
__global__ void k_prep(const float* __restrict__ x, const float* __restrict__ w) {
    __shared__ float xs[128][65];        // used by prepB part only
    int tid = threadIdx.x;               // 256 threads

    if (blockIdx.x < 32) {
        // ---- prepW: weight -> fp16 swizzled tiles ----
        int bx = blockIdx.x;
        int oT = bx >> 3, ic = bx & 7;
#pragma unroll 1
        for (int p = tid; p < 4096; p += 256) {   // 128 o-rows x 32 j2
            int ol = p >> 5, j2 = p & 31;
            int o = oT * 128 + ol;
            int i = ic * 64 + 2 * j2;
            const float* src = w + ((size_t)o * CI + i) * KW;
            float v[10];
#pragma unroll
            for (int q = 0; q < 10; ++q) v[q] = src[q];
            uint32_t off = swz((uint32_t)ol * 128 + j2 * 4);
#pragma unroll
            for (int k = 0; k < KW; ++k) {
                __half2 hv = __floats2half2_rn(v[k], v[5 + k]);
                char* tile = (char*)g_W + (size_t)((k * 4 + oT) * 8 + ic) * TILE_B;
                *(uint32_t*)(tile + off) = *(uint32_t*)&hv;
            }
        }
        return;
    }

    // ---- prepB: x -> fp16 transposed swizzled rows + partial sums ----
    int bx = blockIdx.x - 32;            // b*(8*33) + ic*33 + g
    int g = bx % 33;
    int ic = (bx / 33) & 7;
    int b = bx / (33 * 8);
    // load 64 channels x 128 l (float2 pairs; pairs never straddle bounds)
    for (int e = tid; e < 64 * 64; e += 256) {
        int c = e >> 6, po = e & 63;
        int l = g * 128 - 2 + 2 * po;
        float2 v = make_float2(0.f, 0.f);
        if (l >= 0 && l < LL - 1)
            v = *(const float2*)(x + ((size_t)(b * CI + ic * 64 + c)) * LL + l);
        xs[2 * po][c] = v.x;
        xs[2 * po + 1][c] = v.y;
    }
    __syncthreads();

    // partial sums (race-free; reduced in k_att1)
    {
        int c = tid >> 2, part = tid & 3;
        float s = 0.f;
#pragma unroll
        for (int q = 0; q < 32; ++q) s += xs[part * 32 + q][c];
        s += __shfl_xor_sync(0xFFFFFFFFu, s, 1);
        s += __shfl_xor_sync(0xFFFFFFFFu, s, 2);
        if (part == 0)
            g_avgp[((size_t)b * CI + ic * 64 + c) * 33 + g] = s;
    }

    char* base = (char*)g_Bx + ((size_t)(b * 8 + ic) * BROWS + (size_t)g * 128) * 128;
#pragma unroll
    for (int q = 0; q < 4; ++q) {
        int idx = tid + q * 256;
        int r = idx >> 3, j = idx & 7;
        uint32_t u[4];
#pragma unroll
        for (int p = 0; p < 4; ++p) {
            __half2 hv = __floats2half2_rn(xs[r][j * 8 + 2 * p], xs[r][j * 8 + 2 * p + 1]);
            u[p] = *(uint32_t*)&hv;
        }
        uint32_t off = (uint32_t)(j * 16) ^ (uint32_t)((r & 7) * 16);
        *(uint4*)(base + (size_t)r * 128 + off) = make_uint4(u[0], u[1], u[2], u[3]);
    }
}

// ---------------- kernel 2: attention layer 1 (64 blocks, 4 thr/row) --------------
__global__ void k_att1(
    const float* ka_w1, const float* ka_b1,
    const float* sa_w1, const float* sa_b1,
    const float* ia_w1, const float* ia_b1,
    const float* oa_w1, const float* oa_b1) {
    __shared__ float avgs[CI];
    int bx = blockIdx.x;
    int half = bx & 1, br = (bx >> 1) & 3, b = bx >> 3;
    int t = threadIdx.x;                 // 256 threads
    // reduce partial sums -> means
    for (int c = t; c < CI; c += 256) {
        const float* p = g_avgp + ((size_t)b * CI + c) * 33;
        float s = 0.f;
#pragma unroll
        for (int gg = 0; gg < 33; ++gg) s += p[gg];
        avgs[c] = s * (1.f / (float)LL);
    }
    __syncthreads();

    const float* w1 = br == 0 ? ka_w1 : br == 1 ? sa_w1 : br == 2 ? ia_w1 : oa_w1;
    const float* b1 = br == 0 ? ka_b1 : br == 1 ? sa_b1 : br == 2 ? ia_b1 : oa_b1;
    int row = half * 64 + (t >> 2), q4 = t & 3;
    const float4* wr = (const float4*)(w1 + (size_t)row * CI) + q4 * 32;
    const float4* av = (const float4*)avgs + q4 * 32;
    float s = 0.f;
#pragma unroll 8
    for (int q = 0; q < 32; ++q) s += dot4(wr[q], av[q]);
    s += __shfl_xor_sync(0xFFFFFFFFu, s, 1);
    s += __shfl_xor_sync(0xFFFFFFFFu, s, 2);
    if (q4 == 0)
        g_h[(b * 4 + br) * 128 + row] = fmaxf(s + b1[row], 0.f);
}

// ---------------- kernel 3: attention layer 2 (64 blocks, 4 thr/output) -----------
__global__ void k_att2(
    const float* ka_w2, const float* ka_b2,
    const float* sa_w2, const float* sa_b2,
    const float* ia_w2, const float* ia_b2,
    const float* oa_w2, const float* oa_b2) {
    __shared__ float h[4 * 128];
    __shared__ float sav;
    int bx = blockIdx.x;
    int seg = bx & 7, b = bx >> 3;
    int t = threadIdx.x;                 // 256 threads
    h[t] = g_h[b * 512 + t];
    h[t + 256] = g_h[b * 512 + t + 256];
    __syncthreads();

    int o = seg * 64 + (t >> 2), q4 = t & 3;
    const float4* hoa = (const float4*)(h + 3 * 128) + q4 * 8;
    const float4* woa = (const float4*)(oa_w2 + (size_t)o * 128) + q4 * 8;
    const float4* hia = (const float4*)(h + 2 * 128) + q4 * 8;
    const float4* wia = (const float4*)(ia_w2 + (size_t)o * 128) + q4 * 8;
    float so = 0.f, si = 0.f;
#pragma unroll
    for (int q = 0; q < 8; ++q) {
        so += dot4(woa[q], hoa[q]);
        si += dot4(wia[q], hia[q]);
    }
    so += __shfl_xor_sync(0xFFFFFFFFu, so, 1);
    so += __shfl_xor_sync(0xFFFFFFFFu, so, 2);
    si += __shfl_xor_sync(0xFFFFFFFFu, si, 1);
    si += __shfl_xor_sync(0xFFFFFFFFu, si, 2);

    if (t < 32) {
        float ss = dot4(((const float4*)sa_w2)[t], ((const float4*)(h + 128))[t]);
#pragma unroll
        for (int off = 16; off; off >>= 1) ss += __shfl_xor_sync(0xFFFFFFFFu, ss, off);
        if (t == 0) sav = 1.f / (1.f + expf(-(ss + sa_b2[0])));
    }
    if (seg == 0 && t >= 64 && t < 64 + KW) {
        int kk = t - 64;
        const float4* wka = (const float4*)(ka_w2 + (size_t)kk * 128);
        const float4* hka = (const float4*)h;
        float sk = 0.f;
#pragma unroll 8
        for (int q = 0; q < 32; ++q) sk += dot4(wka[q], hka[q]);
        g_ka[b * KW + kk] = 1.f / (1.f + expf(-(sk + ka_b2[kk])));
    }
    __syncthreads();
    if (q4 == 0) {
        float oav = 1.f / (1.f + expf(-(so + oa_b2[o])));
        float iav = 1.f / (1.f + expf(-(si + ia_b2[o])));
        g_scale[b * CO + o] = sav * iav * oav;
    }
}

// ---------------- kernel 4: HMMA GEMM, 4 warps m64n64, ka via acc rescale ----------
__global__ void __launch_bounds__(128, 2)
k_gemm(const float* __restrict__ bias, float* __restrict__ out) {
    extern __shared__ char sm[];
    uint32_t sbase = smem_u32(sm);
    int tid = threadIdx.x, lane = tid & 31, wid = tid >> 5;
    int bx = blockIdx.x;
    int oT = bx & 3, lT = (bx >> 2) & 31, b = bx >> 7;
    int wm = (wid & 1) * 64, wn = (wid >> 1) * 64;

    const char* wb = (const char*)g_W;
    const char* bb = (const char*)g_Bx;

    float kaf[KW];
#pragma unroll
    for (int k = 0; k < KW; ++k) kaf[k] = g_ka[b * KW + k];

    auto issue = [&](int j, int s) {
        int kw = j >> 3, ic = j & 7;
        const char* sA = wb + (size_t)((kw * 4 + oT) * 8 + ic) * TILE_B;
        const char* sB = bb + ((size_t)(b * 8 + ic) * BROWS + (size_t)(lT * 128 + kw)) * 128;
        uint32_t dA = sbase + s * STAGE_B;
        uint32_t dB = dA + TILE_B;
#pragma unroll
        for (int q = 0; q < 8; ++q) {
            int c = (tid + q * 128) * 16;
            cp16(dA + c, sA + c);
        }
#pragma unroll
        for (int q = 0; q < 8; ++q) {
            int c = (tid + q * 128) * 16;
            cp16(dB + c, sB + c);
        }
    };

    float acc[4][8][4];
#pragma unroll
    for (int mi = 0; mi < 4; ++mi)
#pragma unroll
        for (int ni = 0; ni < 8; ++ni)
#pragma unroll
            for (int r = 0; r < 4; ++r) acc[mi][ni][r] = 0.f;

    int rowA = (lane & 7) + 8 * ((lane >> 3) & 1);
    int colA = (lane >> 4) * 16;
    uint32_t axor = (uint32_t)((lane & 7) << 4);
    int nOffB = ((lane >> 4) & 1) * 8 + (lane & 7);
    int colB = ((lane >> 3) & 1) * 16;

    issue(0, 0); cp_commit();
    issue(1, 1); cp_commit();

#pragma unroll 1
    for (int it = 0; it < NIT; ++it) {
        cp_wait<1>();
        __syncthreads();

        int j2 = it + 2;
        if (j2 < NIT) issue(j2, j2 % 3);
        cp_commit();

        int kw = it >> 3;
        if ((it & 7) == 0 && it > 0) {
            float r = kaf[kw - 1] / kaf[kw];
#pragma unroll
            for (int mi = 0; mi < 4; ++mi)
#pragma unroll
                for (int ni = 0; ni < 8; ++ni)
#pragma unroll
                    for (int q = 0; q < 4; ++q) acc[mi][ni][q] *= r;
        }

        uint32_t bxor = (uint32_t)(((kw + (lane & 7)) & 7) << 4);
        uint32_t sA = sbase + (it % 3) * STAGE_B;
        uint32_t sB = sA + TILE_B;
        uint32_t bRow0 = (uint32_t)(wn + nOffB);
#pragma unroll
        for (int ks = 0; ks < 4; ++ks) {
            uint32_t afr[4][4], bfr[4][4];
#pragma unroll
            for (int mi = 0; mi < 4; ++mi)
                ldmx4(afr[mi][0], afr[mi][1], afr[mi][2], afr[mi][3],
                      (sA + (uint32_t)(wm + mi * 16 + rowA) * 128 + ks * 32 + colA) ^ axor);
#pragma unroll
            for (int nb = 0; nb < 4; ++nb)
                ldmx4(bfr[nb][0], bfr[nb][1], bfr[nb][2], bfr[nb][3],
                      (sB + (bRow0 + nb * 16) * 128 + ks * 32 + colB) ^ bxor);
#pragma unroll
            for (int mi = 0; mi < 4; ++mi)
#pragma unroll
                for (int nb = 0; nb < 4; ++nb) {
                    mma16816(acc[mi][nb * 2],     afr[mi], &bfr[nb][0]);
                    mma16816(acc[mi][nb * 2 + 1], afr[mi], &bfr[nb][2]);
                }
        }
    }

    int r0 = wm + (lane >> 2);
    float ka4 = kaf[KW - 1];
    float scb[4][2], bib[4][2];
#pragma unroll
    for (int mi = 0; mi < 4; ++mi) {
        int o0 = oT * 128 + r0 + mi * 16;
        scb[mi][0] = g_scale[b * CO + o0] * ka4;
        scb[mi][1] = g_scale[b * CO + o0 + 8] * ka4;
        bib[mi][0] = bias[o0];
        bib[mi][1] = bias[o0 + 8];
    }
    float* ob = out + ((size_t)(b * CO + oT * 128)) * LL + lT * 128;
#pragma unroll
    for (int mi = 0; mi < 4; ++mi) {
#pragma unroll
        for (int ni = 0; ni < 8; ++ni) {
            int rr = r0 + mi * 16;
            int cc = wn + (ni >> 1) * 16 + (ni & 1) * 8 + (lane & 3) * 2;
            float2 v0 = make_float2(scb[mi][0] * acc[mi][ni][0] + bib[mi][0],
                                    scb[mi][0] * acc[mi][ni][1] + bib[mi][0]);
            float2 v1 = make_float2(scb[mi][1] * acc[mi][ni][2] + bib[mi][1],
                                    scb[mi][1] * acc[mi][ni][3] + bib[mi][1]);
            *(float2*)(ob + (size_t)rr * LL + cc) = v0;
            *(float2*)(ob + (size_t)(rr + 8) * LL + cc) = v1;
        }
    }
}

// ---------------- launch ----------------
extern "C" void kernel_launch(void* const* d_in, const int* in_sizes, int n_in,
                              void* d_out, int out_size) {
    const float* x      = (const float*)d_in[0];
    const float* weight = (const float*)d_in[1];
    const float* bias   = (const float*)d_in[2];
    const float* ka_w1 = (const float*)d_in[3],  *ka_b1 = (const float*)d_in[4];
    const float* ka_w2 = (const float*)d_in[5],  *ka_b2 = (const float*)d_in[6];
    const float* sa_w1 = (const float*)d_in[7],  *sa_b1 = (const float*)d_in[8];
    const float* sa_w2 = (const float*)d_in[9],  *sa_b2 = (const float*)d_in[10];
    const float* ia_w1 = (const float*)d_in[11], *ia_b1 = (const float*)d_in[12];
    const float* ia_w2 = (const float*)d_in[13], *ia_b2 = (const float*)d_in[14];
    const float* oa_w1 = (const float*)d_in[15], *oa_b1 = (const float*)d_in[16];
    const float* oa_w2 = (const float*)d_in[17], *oa_b2 = (const float*)d_in[18];
    float* out = (float*)d_out;

    cudaFuncSetAttribute(k_gemm, cudaFuncAttributeMaxDynamicSharedMemorySize, GEMM_SMEM);

    k_prep<<<32 + BB * 8 * 33, 256>>>(x, weight);
    k_att1<<<BB * 8, 256>>>(ka_w1, ka_b1, sa_w1, sa_b1, ia_w1, ia_b1, oa_w1, oa_b1);
    k_att2<<<BB * 8, 256>>>(ka_w2, ka_b2, sa_w2, sa_b2, ia_w2, ia_b2, oa_w2, oa_b2);
    k_gemm<<<BB * 32 * 4, 128, GEMM_SMEM>>>(bias, out);
}